// round 8
// baseline (speedup 1.0000x reference)
#include <cuda_runtime.h>

// Problem constants (fixed by the reference setup)
#define BB   2
#define CH   64
#define NH   8
#define DH   8
#define HW   48
#define LL   2304            // HW*HW
#define BCHL (BB*CH*LL)      // 294912

#define LOG2E 1.4426950408889634f

#define EX2F(r,x)     asm("ex2.approx.ftz.f32 %0,%1;"  : "=f"(r) : "f"(x))
#define CVT_TF32(u,x) asm("cvt.rna.tf32.f32 %0,%1;"    : "=r"(u) : "f"(x))

#define MMA_TF32(d0,d1,d2,d3,a0,a1,a2,a3,b0,b1) \
  asm volatile("mma.sync.aligned.m16n8k8.row.col.f32.tf32.tf32.f32 " \
    "{%0,%1,%2,%3},{%4,%5,%6,%7},{%8,%9},{%0,%1,%2,%3};" \
    : "+f"(d0),"+f"(d1),"+f"(d2),"+f"(d3) \
    : "r"(a0),"r"(a1),"r"(a2),"r"(a3),"r"(b0),"r"(b1))

typedef unsigned int u32;

// Scratch (device globals — no allocation allowed)
__device__ float g_qhi[BCHL];   // tf32-hi of q*qscale*log2e
__device__ float g_qlo[BCHL];   // residual
__device__ float g_khi[BCHL];   // tf32-hi of k
__device__ float g_klo[BCHL];
__device__ float g_v  [BCHL];
__device__ float g_zinv[BB*NH*LL];
__device__ float g_op[2][BCHL];
__device__ float g_o [BCHL];

// ---------------------------------------------------------------------------
// K1: fused q/k/v 1x1 convs + tf32 hi/lo splits.  grid = 288 x 256.
// ---------------------------------------------------------------------------
__global__ __launch_bounds__(256) void k_qkv(
    const float* __restrict__ x,
    const float* __restrict__ Wq, const float* __restrict__ bq,
    const float* __restrict__ Wk, const float* __restrict__ bk,
    const float* __restrict__ Wv, const float* __restrict__ bv,
    float* __restrict__ q_out)
{
    __shared__ __align__(16) float sW[3][64*64];
    __shared__ float sb[3][64];
    const int tid = threadIdx.x;
    for (int i = tid; i < 4096; i += 256) {
        sW[0][i] = Wq[i]; sW[1][i] = Wk[i]; sW[2][i] = Wv[i];
    }
    if (tid < 64) { sb[0][tid] = bq[tid]; sb[1][tid] = bk[tid]; sb[2][tid] = bv[tid]; }
    __syncthreads();

    const int col = blockIdx.x * 16 + (tid & 15);
    const int og  = tid >> 4;
    const int b   = col / LL;
    const int l   = col - b * LL;

    const float* xp = x + (size_t)b * CH * LL + l;
    float xr[64];
#pragma unroll
    for (int c = 0; c < 64; c++) xr[c] = xp[c * LL];

    const float qscale = 0.35355339059327373f;  // 8^-0.5

#pragma unroll
    for (int m = 0; m < 3; m++) {
#pragma unroll
        for (int j = 0; j < 4; j++) {
            const int o = og * 4 + j;
            const float4* wr = (const float4*)&sW[m][o * 64];
            float a0 = 0.f, a1 = 0.f, a2 = 0.f, a3 = 0.f;
#pragma unroll
            for (int c4 = 0; c4 < 16; c4++) {
                float4 w = wr[c4];
                a0 = fmaf(w.x, xr[c4*4+0], a0);
                a1 = fmaf(w.y, xr[c4*4+1], a1);
                a2 = fmaf(w.z, xr[c4*4+2], a2);
                a3 = fmaf(w.w, xr[c4*4+3], a3);
            }
            float r = (a0 + a1) + (a2 + a3) + sb[m][o];
            const size_t idx = ((size_t)b * CH + o) * LL + l;
            if (m == 0) {
                float rq = r * qscale;
                q_out[idx] = rq;                 // reference returns the SCALED q
                float t = rq * LOG2E;            // prescaled for EX2
                u32 hb; CVT_TF32(hb, t);
                float hi = __uint_as_float(hb);
                g_qhi[idx] = hi;
                g_qlo[idx] = t - hi;
            } else if (m == 1) {
                u32 hb; CVT_TF32(hb, r);
                float hi = __uint_as_float(hb);
                g_khi[idx] = hi;
                g_klo[idx] = r - hi;
            } else {
                g_v[idx] = r;
            }
        }
    }
}

// ---------------------------------------------------------------------------
// K2 (pass A): Z via tensor logits.  Block = 256 thr (8 warps), each warp owns
// 8 k-columns (fixed B frags) and loops all 144 q-tiles, accumulating
// Z-partials in registers; final 1/Z written directly.
// grid = (bh=16, kblk=36).
// ---------------------------------------------------------------------------
__global__ __launch_bounds__(256) void k_passA()
{
    const int bh = blockIdx.x;
    const int b = bh >> 3, h = bh & 7;
    const size_t base = (size_t)(b * CH + h * DH) * LL;
    const int tid  = threadIdx.x;
    const int lane = tid & 31, wid = tid >> 5;
    const int c4 = lane & 3, gid = lane >> 2;
    const int wk = blockIdx.y * 64 + wid * 8;   // this warp's 8 k-cols

    // Fixed B fragments (K hi/lo)
    const u32 bh0 = __float_as_uint(g_khi[base + (size_t)c4 * LL + wk + gid]);
    const u32 bh1 = __float_as_uint(g_khi[base + (size_t)(c4 + 4) * LL + wk + gid]);
    const u32 bl0 = __float_as_uint(g_klo[base + (size_t)c4 * LL + wk + gid]);
    const u32 bl1 = __float_as_uint(g_klo[base + (size_t)(c4 + 4) * LL + wk + gid]);

    const float* qhi = g_qhi + base;
    const float* qlo = g_qlo + base;
    const size_t r0 = (size_t)c4 * LL, r1 = (size_t)(c4 + 4) * LL;

    float zac0 = 0.f, zac1 = 0.f;
#pragma unroll 2
    for (int qt = 0; qt < 144; qt++) {
        const int q = qt * 16 + gid;
        u32 ah0 = __float_as_uint(qhi[r0 + q]);
        u32 ah1 = __float_as_uint(qhi[r0 + q + 8]);
        u32 ah2 = __float_as_uint(qhi[r1 + q]);
        u32 ah3 = __float_as_uint(qhi[r1 + q + 8]);
        u32 al0 = __float_as_uint(qlo[r0 + q]);
        u32 al1 = __float_as_uint(qlo[r0 + q + 8]);
        u32 al2 = __float_as_uint(qlo[r1 + q]);
        u32 al3 = __float_as_uint(qlo[r1 + q + 8]);
        float c0 = 0.f, c1 = 0.f, c2 = 0.f, c3 = 0.f;
        MMA_TF32(c0,c1,c2,c3, ah0,ah1,ah2,ah3, bh0,bh1);
        MMA_TF32(c0,c1,c2,c3, ah0,ah1,ah2,ah3, bl0,bl1);
        MMA_TF32(c0,c1,c2,c3, al0,al1,al2,al3, bh0,bh1);
        float e0, e1, e2, e3;
        EX2F(e0, c0); EX2F(e1, c1); EX2F(e2, c2); EX2F(e3, c3);
        zac0 += e0 + e2;   // column 2*c4
        zac1 += e1 + e3;   // column 2*c4+1
    }
    // reduce over the 8 gid-lanes sharing each column (stride-4 lanes)
    zac0 += __shfl_xor_sync(0xffffffffu, zac0, 4);
    zac0 += __shfl_xor_sync(0xffffffffu, zac0, 8);
    zac0 += __shfl_xor_sync(0xffffffffu, zac0, 16);
    zac1 += __shfl_xor_sync(0xffffffffu, zac1, 4);
    zac1 += __shfl_xor_sync(0xffffffffu, zac1, 8);
    zac1 += __shfl_xor_sync(0xffffffffu, zac1, 16);
    if (lane < 4) {
        g_zinv[(size_t)bh * LL + wk + 2 * lane]     = 1.0f / zac0;
        g_zinv[(size_t)bh * LL + wk + 2 * lane + 1] = 1.0f / zac1;
    }
}

// ---------------------------------------------------------------------------
// K3 (pass B): tensor logits -> exp -> shuffle relayout -> tensor AV.
// Block = 256 thr (8 warps); warp owns a fixed 16-q tile; block covers 128 q.
// K/V chunks of 128 staged in SMEM (hi/lo tf32 splits; V scaled by 1/Z).
// grid = (bh=16, qblk=18, kseg=2); each kseg covers 1152 k.
// ---------------------------------------------------------------------------
__global__ __launch_bounds__(256) void k_passB()
{
    const int bh = blockIdx.x;
    const int b = bh >> 3, h = bh & 7;
    const size_t base = (size_t)(b * CH + h * DH) * LL;
    const int tid  = threadIdx.x;
    const int lane = tid & 31, wid = tid >> 5;
    const int c4 = lane & 3, gid = lane >> 2;
    const int q0 = blockIdx.y * 128 + wid * 16;
    const int kseg = blockIdx.z;

    // Fixed A fragments (Q hi/lo) for this warp's 16-q tile
    const float* qhi = g_qhi + base;
    const float* qlo = g_qlo + base;
    const size_t r0 = (size_t)c4 * LL, r1 = (size_t)(c4 + 4) * LL;
    const u32 ah0 = __float_as_uint(qhi[r0 + q0 + gid]);
    const u32 ah1 = __float_as_uint(qhi[r0 + q0 + gid + 8]);
    const u32 ah2 = __float_as_uint(qhi[r1 + q0 + gid]);
    const u32 ah3 = __float_as_uint(qhi[r1 + q0 + gid + 8]);
    const u32 al0 = __float_as_uint(qlo[r0 + q0 + gid]);
    const u32 al1 = __float_as_uint(qlo[r0 + q0 + gid + 8]);
    const u32 al2 = __float_as_uint(qlo[r1 + q0 + gid]);
    const u32 al3 = __float_as_uint(qlo[r1 + q0 + gid + 8]);

    const int src1 = (lane & ~3) | (c4 >> 1);
    const int src2 = src1 + 2;
    const bool odd = (c4 & 1);

    // SMEM stages: K [d][136k], V [ch][140k]  (pads keep frag LDS conflict-free)
    __shared__ float skhi[8][136], sklo[8][136];
    __shared__ float svhi[8][140], svlo[8][140];

    float oc0 = 0.f, oc1 = 0.f, oc2 = 0.f, oc3 = 0.f;

    for (int chunk = 0; chunk < 9; chunk++) {
        const int kc = kseg * 1152 + chunk * 128;
        __syncthreads();
        // fill K hi/lo
        for (int i = tid; i < 1024; i += 256) {
            const int d = i >> 7, kk = i & 127;
            skhi[d][kk] = g_khi[base + (size_t)d * LL + kc + kk];
            sklo[d][kk] = g_klo[base + (size_t)d * LL + kc + kk];
        }
        // fill V' = v * zinv, split hi/lo
        for (int i = tid; i < 1024; i += 256) {
            const int ch = i >> 7, kk = i & 127;
            const float zi = g_zinv[(size_t)bh * LL + kc + kk];
            const float vv = g_v[base + (size_t)ch * LL + kc + kk] * zi;
            u32 hb; CVT_TF32(hb, vv);
            const float hi = __uint_as_float(hb);
            svhi[ch][kk] = hi;
            svlo[ch][kk] = vv - hi;
        }
        __syncthreads();

#pragma unroll 2
        for (int kt = 0; kt < 16; kt++) {
            const int kx = kt * 8 + gid;
            const u32 kb0 = __float_as_uint(skhi[c4][kx]);
            const u32 kb1 = __float_as_uint(skhi[c4 + 4][kx]);
            const u32 kl0 = __float_as_uint(sklo[c4][kx]);
            const u32 kl1 = __float_as_uint(sklo[c4 + 4][kx]);

            float c0 = 0.f, c1 = 0.f, c2 = 0.f, c3 = 0.f;
            MMA_TF32(c0,c1,c2,c3, ah0,ah1,ah2,ah3, kb0,kb1);
            MMA_TF32(c0,c1,c2,c3, ah0,ah1,ah2,ah3, kl0,kl1);
            MMA_TF32(c0,c1,c2,c3, al0,al1,al2,al3, kb0,kb1);

            float e0, e1, e2, e3;
            EX2F(e0, c0); EX2F(e1, c1); EX2F(e2, c2); EX2F(e3, c3);

            // relayout C -> A (weights) via quad shuffles
            const float s10 = __shfl_sync(0xffffffffu, e0, src1);
            const float s11 = __shfl_sync(0xffffffffu, e1, src1);
            const float s12 = __shfl_sync(0xffffffffu, e2, src1);
            const float s13 = __shfl_sync(0xffffffffu, e3, src1);
            const float s20 = __shfl_sync(0xffffffffu, e0, src2);
            const float s21 = __shfl_sync(0xffffffffu, e1, src2);
            const float s22 = __shfl_sync(0xffffffffu, e2, src2);
            const float s23 = __shfl_sync(0xffffffffu, e3, src2);
            const float w0 = odd ? s11 : s10;   // (gid,   c4)
            const float w1 = odd ? s13 : s12;   // (gid+8, c4)
            const float w2 = odd ? s21 : s20;   // (gid,   c4+4)
            const float w3 = odd ? s23 : s22;   // (gid+8, c4+4)

            u32 wh0, wh1, wh2, wh3;
            CVT_TF32(wh0, w0); CVT_TF32(wh1, w1); CVT_TF32(wh2, w2); CVT_TF32(wh3, w3);
            const u32 wl0 = __float_as_uint(w0 - __uint_as_float(wh0));
            const u32 wl1 = __float_as_uint(w1 - __uint_as_float(wh1));
            const u32 wl2 = __float_as_uint(w2 - __uint_as_float(wh2));
            const u32 wl3 = __float_as_uint(w3 - __uint_as_float(wh3));

            const int kv0 = kt * 8 + c4, kv1 = kt * 8 + c4 + 4;
            const u32 vh0 = __float_as_uint(svhi[gid][kv0]);
            const u32 vh1 = __float_as_uint(svhi[gid][kv1]);
            const u32 vl0 = __float_as_uint(svlo[gid][kv0]);
            const u32 vl1 = __float_as_uint(svlo[gid][kv1]);

            MMA_TF32(oc0,oc1,oc2,oc3, wh0,wh1,wh2,wh3, vh0,vh1);
            MMA_TF32(oc0,oc1,oc2,oc3, wh0,wh1,wh2,wh3, vl0,vl1);
            MMA_TF32(oc0,oc1,oc2,oc3, wl0,wl1,wl2,wl3, vh0,vh1);
        }
    }

    // O fragment: oc0=(q0+gid, ch=2c4), oc1=(.., 2c4+1), oc2=(q0+gid+8, 2c4), oc3=(.., 2c4+1)
    float* Ob = g_op[kseg] + base;
    Ob[(size_t)(2 * c4)     * LL + q0 + gid]     = oc0;
    Ob[(size_t)(2 * c4 + 1) * LL + q0 + gid]     = oc1;
    Ob[(size_t)(2 * c4)     * LL + q0 + gid + 8] = oc2;
    Ob[(size_t)(2 * c4 + 1) * LL + q0 + gid + 8] = oc3;
}

// ---------------------------------------------------------------------------
// K4: reduce the 2 k-segment partials.
// ---------------------------------------------------------------------------
__global__ __launch_bounds__(256) void k_reduce2()
{
    const int i = blockIdx.x * 256 + threadIdx.x;  // over BCHL/4 = 73728
    float4 a = ((const float4*)g_op[0])[i];
    float4 t = ((const float4*)g_op[1])[i];
    a.x += t.x; a.y += t.y; a.z += t.z; a.w += t.w;
    ((float4*)g_o)[i] = a;
}

// ---------------------------------------------------------------------------
// K5: output 1x1 conv.  grid = 288 x 256.
// ---------------------------------------------------------------------------
__global__ __launch_bounds__(256) void k_oconv(
    const float* __restrict__ Wo, const float* __restrict__ bo,
    float* __restrict__ out)
{
    __shared__ __align__(16) float sW[64*64];
    __shared__ float sb[64];
    const int tid = threadIdx.x;
    for (int i = tid; i < 4096; i += 256) sW[i] = Wo[i];
    if (tid < 64) sb[tid] = bo[tid];
    __syncthreads();

    const int col = blockIdx.x * 16 + (tid & 15);
    const int og  = tid >> 4;
    const int b   = col / LL;
    const int l   = col - b * LL;

    const float* xp = g_o + (size_t)b * CH * LL + l;
    float xr[64];
#pragma unroll
    for (int c = 0; c < 64; c++) xr[c] = xp[c * LL];

#pragma unroll
    for (int j = 0; j < 4; j++) {
        const int o = og * 4 + j;
        const float4* wr = (const float4*)&sW[o * 64];
        float a0 = 0.f, a1 = 0.f, a2 = 0.f, a3 = 0.f;
#pragma unroll
        for (int c4 = 0; c4 < 16; c4++) {
            float4 w = wr[c4];
            a0 = fmaf(w.x, xr[c4*4+0], a0);
            a1 = fmaf(w.y, xr[c4*4+1], a1);
            a2 = fmaf(w.z, xr[c4*4+2], a2);
            a3 = fmaf(w.w, xr[c4*4+3], a3);
        }
        out[((size_t)b * CH + o) * LL + l] = (a0 + a1) + (a2 + a3) + sb[o];
    }
}

// ---------------------------------------------------------------------------
extern "C" void kernel_launch(void* const* d_in, const int* in_sizes, int n_in,
                              void* d_out, int out_size)
{
    const float* x  = (const float*)d_in[0];
    const float* Wq = (const float*)d_in[1];
    const float* bq = (const float*)d_in[2];
    const float* Wk = (const float*)d_in[3];
    const float* bk = (const float*)d_in[4];
    const float* Wv = (const float*)d_in[5];
    const float* bv = (const float*)d_in[6];
    const float* Wo = (const float*)d_in[7];
    const float* bo = (const float*)d_in[8];

    float* out   = (float*)d_out;           // first output: conv result
    float* q_out = (float*)d_out + BCHL;    // second output: scaled q

    k_qkv<<<288, 256>>>(x, Wq, bq, Wk, bk, Wv, bv, q_out);
    k_passA<<<dim3(16, 36), 256>>>();
    k_passB<<<dim3(16, 18, 2), 256>>>();
    k_reduce2<<<288, 256>>>();
    k_oconv<<<288, 256>>>(Wo, bo, out);
}

// round 9
// speedup vs baseline: 1.3977x; 1.3977x over previous
#include <cuda_runtime.h>

// Problem constants (fixed by the reference setup)
#define BB   2
#define CH   64
#define NH   8
#define DH   8
#define HW   48
#define LL   2304            // HW*HW
#define BCHL (BB*CH*LL)      // 294912
#define SEGS 9
#define QSEG 256             // LL/SEGS
#define KSEG 256

#define LOG2E 1.4426950408889634f

// Packed f32x2 helpers (sm_103a FFMA2 path)
#define FMA2(d,a,b,c) asm("fma.rn.f32x2 %0,%1,%2,%3;" : "=l"(d) : "l"(a), "l"(b), "l"(c))
#define MUL2(d,a,b)   asm("mul.rn.f32x2 %0,%1,%2;"    : "=l"(d) : "l"(a), "l"(b))
#define ADD2(d,a,b)   asm("add.rn.f32x2 %0,%1,%2;"    : "=l"(d) : "l"(a), "l"(b))
#define PACK2(d,x,y)  asm("mov.b64 %0,{%1,%2};"        : "=l"(d) : "f"(x), "f"(y))
#define UNPACK2(x,y,d) asm("mov.b64 {%0,%1},%2;"       : "=f"(x), "=f"(y) : "l"(d))
#define EX2F(r,x)     asm("ex2.approx.ftz.f32 %0,%1;"  : "=f"(r) : "f"(x))

typedef unsigned long long u64;

// Scratch (device globals — no allocation allowed)
__device__ float g_q [BCHL];          // q * d^-0.5 * log2(e)  (for EX2)
__device__ float g_k [BCHL];
__device__ float g_v [BCHL];
__device__ float g_o [BCHL];
__device__ float g_Z [SEGS][BB*NH][LL];
__device__ float g_op[SEGS][BCHL];

// ---------------------------------------------------------------------------
// K1: fused q/k/v 1x1 convs.  grid = 288 blocks x 256 thr.
// ---------------------------------------------------------------------------
__global__ __launch_bounds__(256) void k_qkv(
    const float* __restrict__ x,
    const float* __restrict__ Wq, const float* __restrict__ bq,
    const float* __restrict__ Wk, const float* __restrict__ bk,
    const float* __restrict__ Wv, const float* __restrict__ bv,
    float* __restrict__ q_out)
{
    __shared__ __align__(16) float sW[3][64*64];
    __shared__ float sb[3][64];
    const int tid = threadIdx.x;
    for (int i = tid; i < 4096; i += 256) {
        sW[0][i] = Wq[i]; sW[1][i] = Wk[i]; sW[2][i] = Wv[i];
    }
    if (tid < 64) { sb[0][tid] = bq[tid]; sb[1][tid] = bk[tid]; sb[2][tid] = bv[tid]; }
    __syncthreads();

    const int col = blockIdx.x * 16 + (tid & 15);     // 0..4607
    const int og  = tid >> 4;                          // 0..15
    const int b   = col / LL;
    const int l   = col - b * LL;

    const float* xp = x + (size_t)b * CH * LL + l;
    float xr[64];
#pragma unroll
    for (int c = 0; c < 64; c++) xr[c] = xp[c * LL];

    const float qscale = 0.35355339059327373f;  // 8^-0.5

#pragma unroll
    for (int m = 0; m < 3; m++) {
        float* dst = (m == 0) ? g_q : (m == 1) ? g_k : g_v;
#pragma unroll
        for (int j = 0; j < 4; j++) {
            const int o = og * 4 + j;
            const float4* wr = (const float4*)&sW[m][o * 64];
            float a0 = 0.f, a1 = 0.f, a2 = 0.f, a3 = 0.f;
#pragma unroll
            for (int c4 = 0; c4 < 16; c4++) {
                float4 w = wr[c4];
                a0 = fmaf(w.x, xr[c4*4+0], a0);
                a1 = fmaf(w.y, xr[c4*4+1], a1);
                a2 = fmaf(w.z, xr[c4*4+2], a2);
                a3 = fmaf(w.w, xr[c4*4+3], a3);
            }
            float r = (a0 + a1) + (a2 + a3) + sb[m][o];
            const size_t idx = ((size_t)b * CH + o) * LL + l;
            if (m == 0) {
                float rq = r * qscale;
                q_out[idx] = rq;                 // reference returns the SCALED q
                dst[idx]   = rq * LOG2E;         // internal: prescaled for EX2
            } else {
                dst[idx] = r;
            }
        }
    }
}

// ---------------------------------------------------------------------------
// K2 (pass A): partial Z over a q-segment.  4 k-cols/thread (2 packed pairs),
// depth-4 logit trees, quad-unrolled with LDS batched per pair.
// grid = (bh=16, ktile=2, seg=9) x 288 thr.
// ---------------------------------------------------------------------------
__global__ __launch_bounds__(288, 2) void k_passA()
{
    const int bh = blockIdx.x;
    const int b = bh >> 3, h = bh & 7;
    const int tid = threadIdx.x;
    const int k0 = blockIdx.y * 1152 + tid * 4;
    const int seg = blockIdx.z;

    const float* Kb = g_k + (size_t)(b * CH + h * DH) * LL;
    const float* Qb = g_q + (size_t)(b * CH + h * DH) * LL;

    u64 kp0[8], kp1[8];
#pragma unroll
    for (int d = 0; d < 8; d++) {
        float4 kv = *(const float4*)&Kb[d * LL + k0];
        PACK2(kp0[d], kv.x, kv.y);
        PACK2(kp1[d], kv.z, kv.w);
    }

    __shared__ __align__(16) float2 sq[QSEG][8];
    const int q0 = seg * QSEG;
    for (int i = tid; i < QSEG * 8; i += 288) {
        const int d = i >> 8, qq = i & 255;
        float v = Qb[d * LL + q0 + qq];
        sq[qq][d] = make_float2(v, v);
    }
    __syncthreads();

    u64 Z0 = 0ull, Z1 = 0ull;   // packed {0,0}
#pragma unroll 2
    for (int qq = 0; qq < QSEG; qq += 2) {
        // batch both iterations' LDS up front
        const ulonglong2* qr0 = (const ulonglong2*)sq[qq];
        const ulonglong2* qr1 = (const ulonglong2*)sq[qq + 1];
        ulonglong2 qa = qr0[0], qb_ = qr0[1], qc = qr0[2], qd = qr0[3];
        ulonglong2 ra = qr1[0], rb_ = qr1[1], rc = qr1[2], rd = qr1[3];
        {
            u64 u0, t0, u1, t1, l0, l1;
            MUL2(u0, qa.x,  kp0[0]); MUL2(t0, qc.x,  kp0[4]);
            MUL2(u1, qa.x,  kp1[0]); MUL2(t1, qc.x,  kp1[4]);
            FMA2(u0, qa.y,  kp0[1], u0); FMA2(t0, qc.y,  kp0[5], t0);
            FMA2(u1, qa.y,  kp1[1], u1); FMA2(t1, qc.y,  kp1[5], t1);
            FMA2(u0, qb_.x, kp0[2], u0); FMA2(t0, qd.x,  kp0[6], t0);
            FMA2(u1, qb_.x, kp1[2], u1); FMA2(t1, qd.x,  kp1[6], t1);
            FMA2(u0, qb_.y, kp0[3], u0); FMA2(t0, qd.y,  kp0[7], t0);
            FMA2(u1, qb_.y, kp1[3], u1); FMA2(t1, qd.y,  kp1[7], t1);
            ADD2(l0, u0, t0);
            ADD2(l1, u1, t1);
            float a0, a1, b0, b1, e0, e1, e2, e3;
            UNPACK2(a0, a1, l0);
            UNPACK2(b0, b1, l1);
            EX2F(e0, a0); EX2F(e1, a1); EX2F(e2, b0); EX2F(e3, b1);
            u64 w0, w1;
            PACK2(w0, e0, e1);
            PACK2(w1, e2, e3);
            ADD2(Z0, Z0, w0);
            ADD2(Z1, Z1, w1);
        }
        {
            u64 u0, t0, u1, t1, l0, l1;
            MUL2(u0, ra.x,  kp0[0]); MUL2(t0, rc.x,  kp0[4]);
            MUL2(u1, ra.x,  kp1[0]); MUL2(t1, rc.x,  kp1[4]);
            FMA2(u0, ra.y,  kp0[1], u0); FMA2(t0, rc.y,  kp0[5], t0);
            FMA2(u1, ra.y,  kp1[1], u1); FMA2(t1, rc.y,  kp1[5], t1);
            FMA2(u0, rb_.x, kp0[2], u0); FMA2(t0, rd.x,  kp0[6], t0);
            FMA2(u1, rb_.x, kp1[2], u1); FMA2(t1, rd.x,  kp1[6], t1);
            FMA2(u0, rb_.y, kp0[3], u0); FMA2(t0, rd.y,  kp0[7], t0);
            FMA2(u1, rb_.y, kp1[3], u1); FMA2(t1, rd.y,  kp1[7], t1);
            ADD2(l0, u0, t0);
            ADD2(l1, u1, t1);
            float a0, a1, b0, b1, e0, e1, e2, e3;
            UNPACK2(a0, a1, l0);
            UNPACK2(b0, b1, l1);
            EX2F(e0, a0); EX2F(e1, a1); EX2F(e2, b0); EX2F(e3, b1);
            u64 w0, w1;
            PACK2(w0, e0, e1);
            PACK2(w1, e2, e3);
            ADD2(Z0, Z0, w0);
            ADD2(Z1, Z1, w1);
        }
    }
    float z0, z1, z2, z3;
    UNPACK2(z0, z1, Z0);
    UNPACK2(z2, z3, Z1);
    *(float4*)&g_Z[seg][bh][k0] = make_float4(z0, z1, z2, z3);
}

// ---------------------------------------------------------------------------
// K3 (pass B): partial o over a k-segment.  4 q-cols/thread, fused zsum into
// the SMEM fill, depth-4 trees, quad-unrolled with LDS batched per pair.
// grid = (bh=16, qtile=2, seg=9) x 288 thr.
// ---------------------------------------------------------------------------
__global__ __launch_bounds__(288, 2) void k_passB()
{
    const int bh = blockIdx.x;
    const int b = bh >> 3, h = bh & 7;
    const int tid = threadIdx.x;
    const int q0 = blockIdx.y * 1152 + tid * 4;
    const int seg = blockIdx.z;

    const float* Qb = g_q + (size_t)(b * CH + h * DH) * LL;
    const float* Kb = g_k + (size_t)(b * CH + h * DH) * LL;
    const float* Vb = g_v + (size_t)(b * CH + h * DH) * LL;

    u64 qp0[8], qp1[8];
#pragma unroll
    for (int d = 0; d < 8; d++) {
        float4 qv = *(const float4*)&Qb[d * LL + q0];
        PACK2(qp0[d], qv.x, qv.y);
        PACK2(qp1[d], qv.z, qv.w);
    }

    __shared__ __align__(16) float2 sk[KSEG][8];
    __shared__ __align__(16) float2 sv[KSEG][8];
    const int kb = seg * KSEG;
    if (tid < KSEG) {
        const int kk = tid;
        float z = 0.f;
#pragma unroll
        for (int s = 0; s < SEGS; s++) z += g_Z[s][bh][kb + kk];
        const float inv = 1.0f / z;
#pragma unroll
        for (int d = 0; d < 8; d++) {
            float kval = Kb[d * LL + kb + kk];
            float vval = Vb[d * LL + kb + kk] * inv;
            sk[kk][d] = make_float2(kval, kval);
            sv[kk][d] = make_float2(vval, vval);
        }
    }
    __syncthreads();

    u64 o0[8], o1[8];
#pragma unroll
    for (int d = 0; d < 8; d++) { o0[d] = 0ull; o1[d] = 0ull; }

#pragma unroll 2
    for (int kk = 0; kk < KSEG; kk += 2) {
        // batch both iterations' K LDS up front (V loaded after exp is ready)
        const ulonglong2* kr0 = (const ulonglong2*)sk[kk];
        const ulonglong2* kr1 = (const ulonglong2*)sk[kk + 1];
        ulonglong2 ka = kr0[0], kb_ = kr0[1], kc = kr0[2], kd = kr0[3];
        ulonglong2 ma = kr1[0], mb_ = kr1[1], mc = kr1[2], md = kr1[3];
        const ulonglong2* vr0 = (const ulonglong2*)sv[kk];
        const ulonglong2* vr1 = (const ulonglong2*)sv[kk + 1];
        {
            u64 u0, t0, u1, t1, l0, l1;
            MUL2(u0, qp0[0], ka.x);  MUL2(t0, qp0[4], kc.x);
            MUL2(u1, qp1[0], ka.x);  MUL2(t1, qp1[4], kc.x);
            FMA2(u0, qp0[1], ka.y,  u0); FMA2(t0, qp0[5], kc.y,  t0);
            FMA2(u1, qp1[1], ka.y,  u1); FMA2(t1, qp1[5], kc.y,  t1);
            FMA2(u0, qp0[2], kb_.x, u0); FMA2(t0, qp0[6], kd.x,  t0);
            FMA2(u1, qp1[2], kb_.x, u1); FMA2(t1, qp1[6], kd.x,  t1);
            FMA2(u0, qp0[3], kb_.y, u0); FMA2(t0, qp0[7], kd.y,  t0);
            FMA2(u1, qp1[3], kb_.y, u1); FMA2(t1, qp1[7], kd.y,  t1);
            ADD2(l0, u0, t0);
            ADD2(l1, u1, t1);
            float a0, a1, b0, b1, e0, e1, e2, e3;
            UNPACK2(a0, a1, l0);
            UNPACK2(b0, b1, l1);
            EX2F(e0, a0); EX2F(e1, a1); EX2F(e2, b0); EX2F(e3, b1);
            u64 w0, w1;
            PACK2(w0, e0, e1);
            PACK2(w1, e2, e3);
            ulonglong2 va = vr0[0], vb_ = vr0[1], vc = vr0[2], vd = vr0[3];
            FMA2(o0[0], w0, va.x,  o0[0]); FMA2(o1[0], w1, va.x,  o1[0]);
            FMA2(o0[1], w0, va.y,  o0[1]); FMA2(o1[1], w1, va.y,  o1[1]);
            FMA2(o0[2], w0, vb_.x, o0[2]); FMA2(o1[2], w1, vb_.x, o1[2]);
            FMA2(o0[3], w0, vb_.y, o0[3]); FMA2(o1[3], w1, vb_.y, o1[3]);
            FMA2(o0[4], w0, vc.x,  o0[4]); FMA2(o1[4], w1, vc.x,  o1[4]);
            FMA2(o0[5], w0, vc.y,  o0[5]); FMA2(o1[5], w1, vc.y,  o1[5]);
            FMA2(o0[6], w0, vd.x,  o0[6]); FMA2(o1[6], w1, vd.x,  o1[6]);
            FMA2(o0[7], w0, vd.y,  o0[7]); FMA2(o1[7], w1, vd.y,  o1[7]);
        }
        {
            u64 u0, t0, u1, t1, l0, l1;
            MUL2(u0, qp0[0], ma.x);  MUL2(t0, qp0[4], mc.x);
            MUL2(u1, qp1[0], ma.x);  MUL2(t1, qp1[4], mc.x);
            FMA2(u0, qp0[1], ma.y,  u0); FMA2(t0, qp0[5], mc.y,  t0);
            FMA2(u1, qp1[1], ma.y,  u1); FMA2(t1, qp1[5], mc.y,  t1);
            FMA2(u0, qp0[2], mb_.x, u0); FMA2(t0, qp0[6], md.x,  t0);
            FMA2(u1, qp1[2], mb_.x, u1); FMA2(t1, qp1[6], md.x,  t1);
            FMA2(u0, qp0[3], mb_.y, u0); FMA2(t0, qp0[7], md.y,  t0);
            FMA2(u1, qp1[3], mb_.y, u1); FMA2(t1, qp1[7], md.y,  t1);
            ADD2(l0, u0, t0);
            ADD2(l1, u1, t1);
            float a0, a1, b0, b1, e0, e1, e2, e3;
            UNPACK2(a0, a1, l0);
            UNPACK2(b0, b1, l1);
            EX2F(e0, a0); EX2F(e1, a1); EX2F(e2, b0); EX2F(e3, b1);
            u64 w0, w1;
            PACK2(w0, e0, e1);
            PACK2(w1, e2, e3);
            ulonglong2 va = vr1[0], vb_ = vr1[1], vc = vr1[2], vd = vr1[3];
            FMA2(o0[0], w0, va.x,  o0[0]); FMA2(o1[0], w1, va.x,  o1[0]);
            FMA2(o0[1], w0, va.y,  o0[1]); FMA2(o1[1], w1, va.y,  o1[1]);
            FMA2(o0[2], w0, vb_.x, o0[2]); FMA2(o1[2], w1, vb_.x, o1[2]);
            FMA2(o0[3], w0, vb_.y, o0[3]); FMA2(o1[3], w1, vb_.y, o1[3]);
            FMA2(o0[4], w0, vc.x,  o0[4]); FMA2(o1[4], w1, vc.x,  o1[4]);
            FMA2(o0[5], w0, vc.y,  o0[5]); FMA2(o1[5], w1, vc.y,  o1[5]);
            FMA2(o0[6], w0, vd.x,  o0[6]); FMA2(o1[6], w1, vd.x,  o1[6]);
            FMA2(o0[7], w0, vd.y,  o0[7]); FMA2(o1[7], w1, vd.y,  o1[7]);
        }
    }

    float* Ob = g_op[seg] + (size_t)(b * CH + h * DH) * LL;
#pragma unroll
    for (int d = 0; d < 8; d++) {
        float x0, x1, x2, x3;
        UNPACK2(x0, x1, o0[d]);
        UNPACK2(x2, x3, o1[d]);
        *(float4*)&Ob[d * LL + q0] = make_float4(x0, x1, x2, x3);
    }
}

// ---------------------------------------------------------------------------
// K4: reduce o partials across the 9 k-segments (streaming, coalesced).
// float2 per thread, 576 blocks — 2x threads for latency hiding.
// ---------------------------------------------------------------------------
__global__ __launch_bounds__(256) void k_reduce()
{
    const int i = blockIdx.x * 256 + threadIdx.x;  // over BCHL/2 = 147456
    float2 a = ((const float2*)g_op[0])[i];
#pragma unroll
    for (int s = 1; s < SEGS; s++) {
        float2 t = ((const float2*)g_op[s])[i];
        a.x += t.x; a.y += t.y;
    }
    ((float2*)g_o)[i] = a;
}

// ---------------------------------------------------------------------------
// K5: output 1x1 conv.  grid = 288 blocks x 256 thr.
// ---------------------------------------------------------------------------
__global__ __launch_bounds__(256) void k_oconv(
    const float* __restrict__ Wo, const float* __restrict__ bo,
    float* __restrict__ out)
{
    __shared__ __align__(16) float sW[64*64];
    __shared__ float sb[64];
    const int tid = threadIdx.x;
    for (int i = tid; i < 4096; i += 256) sW[i] = Wo[i];
    if (tid < 64) sb[tid] = bo[tid];
    __syncthreads();

    const int col = blockIdx.x * 16 + (tid & 15);
    const int og  = tid >> 4;
    const int b   = col / LL;
    const int l   = col - b * LL;

    const float* xp = g_o + (size_t)b * CH * LL + l;
    float xr[64];
#pragma unroll
    for (int c = 0; c < 64; c++) xr[c] = xp[c * LL];

#pragma unroll
    for (int j = 0; j < 4; j++) {
        const int o = og * 4 + j;
        const float4* wr = (const float4*)&sW[o * 64];
        float a0 = 0.f, a1 = 0.f, a2 = 0.f, a3 = 0.f;
#pragma unroll
        for (int c4 = 0; c4 < 16; c4++) {
            float4 w = wr[c4];
            a0 = fmaf(w.x, xr[c4*4+0], a0);
            a1 = fmaf(w.y, xr[c4*4+1], a1);
            a2 = fmaf(w.z, xr[c4*4+2], a2);
            a3 = fmaf(w.w, xr[c4*4+3], a3);
        }
        out[((size_t)b * CH + o) * LL + l] = (a0 + a1) + (a2 + a3) + sb[o];
    }
}

// ---------------------------------------------------------------------------
extern "C" void kernel_launch(void* const* d_in, const int* in_sizes, int n_in,
                              void* d_out, int out_size)
{
    const float* x  = (const float*)d_in[0];
    const float* Wq = (const float*)d_in[1];
    const float* bq = (const float*)d_in[2];
    const float* Wk = (const float*)d_in[3];
    const float* bk = (const float*)d_in[4];
    const float* Wv = (const float*)d_in[5];
    const float* bv = (const float*)d_in[6];
    const float* Wo = (const float*)d_in[7];
    const float* bo = (const float*)d_in[8];

    float* out   = (float*)d_out;           // first output: conv result
    float* q_out = (float*)d_out + BCHL;    // second output: scaled q

    k_qkv<<<288, 256>>>(x, Wq, bq, Wk, bk, Wv, bv, q_out);
    k_passA<<<dim3(16, 2, SEGS), 288>>>();
    k_passB<<<dim3(16, 2, SEGS), 288>>>();
    k_reduce<<<576, 256>>>();
    k_oconv<<<288, 256>>>(Wo, bo, out);
}

// round 10
// speedup vs baseline: 1.7998x; 1.2877x over previous
#include <cuda_runtime.h>
#include <cuda_fp16.h>

// Problem constants (fixed by the reference setup)
#define BB   2
#define CH   64
#define NH   8
#define DH   8
#define HW   48
#define LL   2304            // HW*HW
#define BCHL (BB*CH*LL)      // 294912
#define SEGS 9
#define QSEG 256             // LL/SEGS

#define LOG2E 1.4426950408889634f

// Packed f32x2 helpers (sm_103a FFMA2 path) — used by scalar passA
#define FMA2(d,a,b,c) asm("fma.rn.f32x2 %0,%1,%2,%3;" : "=l"(d) : "l"(a), "l"(b), "l"(c))
#define MUL2(d,a,b)   asm("mul.rn.f32x2 %0,%1,%2;"    : "=l"(d) : "l"(a), "l"(b))
#define ADD2(d,a,b)   asm("add.rn.f32x2 %0,%1,%2;"    : "=l"(d) : "l"(a), "l"(b))
#define PACK2(d,x,y)  asm("mov.b64 %0,{%1,%2};"        : "=l"(d) : "f"(x), "f"(y))
#define UNPACK2(x,y,d) asm("mov.b64 {%0,%1},%2;"       : "=f"(x), "=f"(y) : "l"(d))
#define EX2F(r,x)     asm("ex2.approx.ftz.f32 %0,%1;"  : "=f"(r) : "f"(x))
#define CVT_TF32(u,x) asm("cvt.rna.tf32.f32 %0,%1;"    : "=r"(u) : "f"(x))
// d = {hi=cvt(a), lo=cvt(b)}
#define PACK_F16X2(d,a,b) asm("cvt.rn.f16x2.f32 %0,%1,%2;" : "=r"(d) : "f"(a), "f"(b))

#define MMA_TF32(d0,d1,d2,d3,a0,a1,a2,a3,b0,b1) \
  asm volatile("mma.sync.aligned.m16n8k8.row.col.f32.tf32.tf32.f32 " \
    "{%0,%1,%2,%3},{%4,%5,%6,%7},{%8,%9},{%0,%1,%2,%3};" \
    : "+f"(d0),"+f"(d1),"+f"(d2),"+f"(d3) \
    : "r"(a0),"r"(a1),"r"(a2),"r"(a3),"r"(b0),"r"(b1))

#define MMA_F16(d0,d1,d2,d3,a0,a1,a2,a3,b0,b1) \
  asm volatile("mma.sync.aligned.m16n8k16.row.col.f32.f16.f16.f32 " \
    "{%0,%1,%2,%3},{%4,%5,%6,%7},{%8,%9},{%0,%1,%2,%3};" \
    : "+f"(d0),"+f"(d1),"+f"(d2),"+f"(d3) \
    : "r"(a0),"r"(a1),"r"(a2),"r"(a3),"r"(b0),"r"(b1))

typedef unsigned long long u64;
typedef unsigned int u32;

// Scratch (device globals — no allocation allowed)
__device__ float g_q [BCHL];          // q * d^-0.5 * log2(e)  (for EX2)
__device__ float g_k [BCHL];
__device__ float g_v [BCHL];
__device__ float g_o [BCHL];
__device__ float g_Z [SEGS][BB*NH][LL];
__device__ float g_zinv[BB*NH*LL];
__device__ float g_op[2][BCHL];

// ---------------------------------------------------------------------------
// K1: fused q/k/v 1x1 convs.  grid = 288 blocks x 256 thr.  (R7, proven)
// ---------------------------------------------------------------------------
__global__ __launch_bounds__(256) void k_qkv(
    const float* __restrict__ x,
    const float* __restrict__ Wq, const float* __restrict__ bq,
    const float* __restrict__ Wk, const float* __restrict__ bk,
    const float* __restrict__ Wv, const float* __restrict__ bv,
    float* __restrict__ q_out)
{
    __shared__ __align__(16) float sW[3][64*64];
    __shared__ float sb[3][64];
    const int tid = threadIdx.x;
    for (int i = tid; i < 4096; i += 256) {
        sW[0][i] = Wq[i]; sW[1][i] = Wk[i]; sW[2][i] = Wv[i];
    }
    if (tid < 64) { sb[0][tid] = bq[tid]; sb[1][tid] = bk[tid]; sb[2][tid] = bv[tid]; }
    __syncthreads();

    const int col = blockIdx.x * 16 + (tid & 15);
    const int og  = tid >> 4;
    const int b   = col / LL;
    const int l   = col - b * LL;

    const float* xp = x + (size_t)b * CH * LL + l;
    float xr[64];
#pragma unroll
    for (int c = 0; c < 64; c++) xr[c] = xp[c * LL];

    const float qscale = 0.35355339059327373f;  // 8^-0.5

#pragma unroll
    for (int m = 0; m < 3; m++) {
        float* dst = (m == 0) ? g_q : (m == 1) ? g_k : g_v;
#pragma unroll
        for (int j = 0; j < 4; j++) {
            const int o = og * 4 + j;
            const float4* wr = (const float4*)&sW[m][o * 64];
            float a0 = 0.f, a1 = 0.f, a2 = 0.f, a3 = 0.f;
#pragma unroll
            for (int c4 = 0; c4 < 16; c4++) {
                float4 w = wr[c4];
                a0 = fmaf(w.x, xr[c4*4+0], a0);
                a1 = fmaf(w.y, xr[c4*4+1], a1);
                a2 = fmaf(w.z, xr[c4*4+2], a2);
                a3 = fmaf(w.w, xr[c4*4+3], a3);
            }
            float r = (a0 + a1) + (a2 + a3) + sb[m][o];
            const size_t idx = ((size_t)b * CH + o) * LL + l;
            if (m == 0) {
                float rq = r * qscale;
                q_out[idx] = rq;                 // reference returns the SCALED q
                dst[idx]   = rq * LOG2E;         // internal: prescaled for EX2
            } else {
                dst[idx] = r;
            }
        }
    }
}

// ---------------------------------------------------------------------------
// K2 (pass A): scalar packed FFMA2 (R7, proven).  grid = (16,2,9) x 288.
// ---------------------------------------------------------------------------
__global__ __launch_bounds__(288) void k_passA()
{
    const int bh = blockIdx.x;
    const int b = bh >> 3, h = bh & 7;
    const int tid = threadIdx.x;
    const int k0 = blockIdx.y * 1152 + tid * 4;
    const int seg = blockIdx.z;

    const float* Kb = g_k + (size_t)(b * CH + h * DH) * LL;
    const float* Qb = g_q + (size_t)(b * CH + h * DH) * LL;

    u64 kp0[8], kp1[8];
#pragma unroll
    for (int d = 0; d < 8; d++) {
        float4 kv = *(const float4*)&Kb[d * LL + k0];
        PACK2(kp0[d], kv.x, kv.y);
        PACK2(kp1[d], kv.z, kv.w);
    }

    __shared__ __align__(16) float2 sq[QSEG][8];
    const int q0 = seg * QSEG;
    for (int i = tid; i < QSEG * 8; i += 288) {
        const int d = i >> 8, qq = i & 255;
        float v = Qb[d * LL + q0 + qq];
        sq[qq][d] = make_float2(v, v);
    }
    __syncthreads();

    u64 Z0 = 0ull, Z1 = 0ull;
#pragma unroll 2
    for (int qq = 0; qq < QSEG; qq += 2) {
        const ulonglong2* qr0 = (const ulonglong2*)sq[qq];
        const ulonglong2* qr1 = (const ulonglong2*)sq[qq + 1];
        ulonglong2 qa = qr0[0], qb_ = qr0[1], qc = qr0[2], qd = qr0[3];
        ulonglong2 ra = qr1[0], rb_ = qr1[1], rc = qr1[2], rd = qr1[3];
        {
            u64 u0, t0, u1, t1, l0, l1;
            MUL2(u0, qa.x,  kp0[0]); MUL2(t0, qc.x,  kp0[4]);
            MUL2(u1, qa.x,  kp1[0]); MUL2(t1, qc.x,  kp1[4]);
            FMA2(u0, qa.y,  kp0[1], u0); FMA2(t0, qc.y,  kp0[5], t0);
            FMA2(u1, qa.y,  kp1[1], u1); FMA2(t1, qc.y,  kp1[5], t1);
            FMA2(u0, qb_.x, kp0[2], u0); FMA2(t0, qd.x,  kp0[6], t0);
            FMA2(u1, qb_.x, kp1[2], u1); FMA2(t1, qd.x,  kp1[6], t1);
            FMA2(u0, qb_.y, kp0[3], u0); FMA2(t0, qd.y,  kp0[7], t0);
            FMA2(u1, qb_.y, kp1[3], u1); FMA2(t1, qd.y,  kp1[7], t1);
            ADD2(l0, u0, t0);
            ADD2(l1, u1, t1);
            float a0, a1, b0, b1, e0, e1, e2, e3;
            UNPACK2(a0, a1, l0);
            UNPACK2(b0, b1, l1);
            EX2F(e0, a0); EX2F(e1, a1); EX2F(e2, b0); EX2F(e3, b1);
            u64 w0, w1;
            PACK2(w0, e0, e1);
            PACK2(w1, e2, e3);
            ADD2(Z0, Z0, w0);
            ADD2(Z1, Z1, w1);
        }
        {
            u64 u0, t0, u1, t1, l0, l1;
            MUL2(u0, ra.x,  kp0[0]); MUL2(t0, rc.x,  kp0[4]);
            MUL2(u1, ra.x,  kp1[0]); MUL2(t1, rc.x,  kp1[4]);
            FMA2(u0, ra.y,  kp0[1], u0); FMA2(t0, rc.y,  kp0[5], t0);
            FMA2(u1, ra.y,  kp1[1], u1); FMA2(t1, rc.y,  kp1[5], t1);
            FMA2(u0, rb_.x, kp0[2], u0); FMA2(t0, rd.x,  kp0[6], t0);
            FMA2(u1, rb_.x, kp1[2], u1); FMA2(t1, rd.x,  kp1[6], t1);
            FMA2(u0, rb_.y, kp0[3], u0); FMA2(t0, rd.y,  kp0[7], t0);
            FMA2(u1, rb_.y, kp1[3], u1); FMA2(t1, rd.y,  kp1[7], t1);
            ADD2(l0, u0, t0);
            ADD2(l1, u1, t1);
            float a0, a1, b0, b1, e0, e1, e2, e3;
            UNPACK2(a0, a1, l0);
            UNPACK2(b0, b1, l1);
            EX2F(e0, a0); EX2F(e1, a1); EX2F(e2, b0); EX2F(e3, b1);
            u64 w0, w1;
            PACK2(w0, e0, e1);
            PACK2(w1, e2, e3);
            ADD2(Z0, Z0, w0);
            ADD2(Z1, Z1, w1);
        }
    }
    float z0, z1, z2, z3;
    UNPACK2(z0, z1, Z0);
    UNPACK2(z2, z3, Z1);
    *(float4*)&g_Z[seg][bh][k0] = make_float4(z0, z1, z2, z3);
}

// ---------------------------------------------------------------------------
// K3: sum Z partials -> 1/Z per (bh, k).  36864 threads.
// ---------------------------------------------------------------------------
__global__ __launch_bounds__(256) void k_zsum()
{
    const int t = blockIdx.x * 256 + threadIdx.x;  // == bh*LL + k
    const float* Zf = (const float*)g_Z;
    float z = 0.f;
#pragma unroll
    for (int s = 0; s < SEGS; s++) z += Zf[(size_t)s * (BB*NH) * LL + t];
    g_zinv[t] = 1.0f / z;
}

// ---------------------------------------------------------------------------
// K4 (pass B): tensor-core version.  Warp owns a 16-q tile; per 16-k step:
// 3x tf32 mma (hi/lo split) logits -> EX2 -> in-place cvt to f16 A-frag
// (FlashAttention relayout: C of m16n8k8 == A of m16n8k16) -> 3x f16 mma
// (wh*vh + wh*vl + wl*vh) with V' = v/Z staged in SMEM as f16 hi/lo.
// grid = (bh=16, qblk=18, kseg=2) x 256 thr.
// ---------------------------------------------------------------------------
__global__ __launch_bounds__(256) void k_passB()
{
    const int bh = blockIdx.x;
    const int b = bh >> 3, h = bh & 7;
    const size_t base = (size_t)(b * CH + h * DH) * LL;
    const int tid  = threadIdx.x;
    const int lane = tid & 31, wid = tid >> 5;
    const int c4 = lane & 3, gid = lane >> 2;
    const int q0 = blockIdx.y * 128 + wid * 16;
    const int kseg = blockIdx.z;

    // Q A-fragments (tf32 hi + f32 residual), rows=q, cols=d
    u32 ah[4], al[4];
    {
        float f0 = g_q[base + (size_t)c4 * LL + q0 + gid];
        float f1 = g_q[base + (size_t)c4 * LL + q0 + gid + 8];
        float f2 = g_q[base + (size_t)(c4 + 4) * LL + q0 + gid];
        float f3 = g_q[base + (size_t)(c4 + 4) * LL + q0 + gid + 8];
        CVT_TF32(ah[0], f0); al[0] = __float_as_uint(f0 - __uint_as_float(ah[0]));
        CVT_TF32(ah[1], f1); al[1] = __float_as_uint(f1 - __uint_as_float(ah[1]));
        CVT_TF32(ah[2], f2); al[2] = __float_as_uint(f2 - __uint_as_float(ah[2]));
        CVT_TF32(ah[3], f3); al[3] = __float_as_uint(f3 - __uint_as_float(ah[3]));
    }

    __shared__ float  skhi[8][136], sklo[8][136];
    __shared__ __half svh [8][136], svl [8][136];

    const int fkk = tid & 127;      // fixed k column this thread fills
    const int fd0 = tid >> 7;       // starting row (0/1), step 2

    float oc0 = 0.f, oc1 = 0.f, oc2 = 0.f, oc3 = 0.f;

    for (int chunk = 0; chunk < 9; chunk++) {
        const int kc = kseg * 1152 + chunk * 128;
        __syncthreads();
        {
            const float zi = g_zinv[(size_t)bh * LL + kc + fkk];
#pragma unroll
            for (int j = 0; j < 4; j++) {
                const int d = fd0 + 2 * j;
                float kvf = g_k[base + (size_t)d * LL + kc + fkk];
                u32 hb; CVT_TF32(hb, kvf);
                float hi = __uint_as_float(hb);
                skhi[d][fkk] = hi;
                sklo[d][fkk] = kvf - hi;
                float vv = g_v[base + (size_t)d * LL + kc + fkk] * zi;
                __half vh = __float2half_rn(vv);
                svh[d][fkk] = vh;
                svl[d][fkk] = __float2half_rn(vv - __half2float(vh));
            }
        }
        __syncthreads();

#pragma unroll
        for (int kt = 0; kt < 8; kt++) {
            const int kx0 = kt * 16 + gid;
            const int kx1 = kx0 + 8;
            const u32 b00 = __float_as_uint(skhi[c4][kx0]);
            const u32 b01 = __float_as_uint(skhi[c4 + 4][kx0]);
            const u32 l00 = __float_as_uint(sklo[c4][kx0]);
            const u32 l01 = __float_as_uint(sklo[c4 + 4][kx0]);
            const u32 b10 = __float_as_uint(skhi[c4][kx1]);
            const u32 b11 = __float_as_uint(skhi[c4 + 4][kx1]);
            const u32 l10 = __float_as_uint(sklo[c4][kx1]);
            const u32 l11 = __float_as_uint(sklo[c4 + 4][kx1]);

            float p0 = 0.f, p1 = 0.f, p2 = 0.f, p3 = 0.f;
            MMA_TF32(p0,p1,p2,p3, ah[0],ah[1],ah[2],ah[3], b00,b01);
            MMA_TF32(p0,p1,p2,p3, ah[0],ah[1],ah[2],ah[3], l00,l01);
            MMA_TF32(p0,p1,p2,p3, al[0],al[1],al[2],al[3], b00,b01);
            float r0 = 0.f, r1 = 0.f, r2 = 0.f, r3 = 0.f;
            MMA_TF32(r0,r1,r2,r3, ah[0],ah[1],ah[2],ah[3], b10,b11);
            MMA_TF32(r0,r1,r2,r3, ah[0],ah[1],ah[2],ah[3], l10,l11);
            MMA_TF32(r0,r1,r2,r3, al[0],al[1],al[2],al[3], b10,b11);

            float e0,e1,e2,e3,f0,f1,f2,f3;
            EX2F(e0,p0); EX2F(e1,p1); EX2F(e2,p2); EX2F(e3,p3);
            EX2F(f0,r0); EX2F(f1,r1); EX2F(f2,r2); EX2F(f3,r3);

            // wh: f16 A-fragment (C layout == A layout, no shuffles)
            u32 wh0, wh1, wh2, wh3;
            PACK_F16X2(wh0, e1, e0);
            PACK_F16X2(wh1, e3, e2);
            PACK_F16X2(wh2, f1, f0);
            PACK_F16X2(wh3, f3, f2);

            // wl: f16 residual fragment
            u32 wl0, wl1, wl2, wl3;
            {
                float2 g;
                g = __half22float2(*reinterpret_cast<__half2*>(&wh0));
                PACK_F16X2(wl0, e1 - g.y, e0 - g.x);
                g = __half22float2(*reinterpret_cast<__half2*>(&wh1));
                PACK_F16X2(wl1, e3 - g.y, e2 - g.x);
                g = __half22float2(*reinterpret_cast<__half2*>(&wh2));
                PACK_F16X2(wl2, f1 - g.y, f0 - g.x);
                g = __half22float2(*reinterpret_cast<__half2*>(&wh3));
                PACK_F16X2(wl3, f3 - g.y, f2 - g.x);
            }

            // V' B-fragments (f16 hi/lo): b0 = k rows {2c4,2c4+1}, b1 = +8
            const u32 vh0 = *reinterpret_cast<const u32*>(&svh[gid][kt * 16 + 2 * c4]);
            const u32 vh1 = *reinterpret_cast<const u32*>(&svh[gid][kt * 16 + 2 * c4 + 8]);
            const u32 vl0 = *reinterpret_cast<const u32*>(&svl[gid][kt * 16 + 2 * c4]);
            const u32 vl1 = *reinterpret_cast<const u32*>(&svl[gid][kt * 16 + 2 * c4 + 8]);

            MMA_F16(oc0,oc1,oc2,oc3, wh0,wh1,wh2,wh3, vh0,vh1);
            MMA_F16(oc0,oc1,oc2,oc3, wh0,wh1,wh2,wh3, vl0,vl1);
            MMA_F16(oc0,oc1,oc2,oc3, wl0,wl1,wl2,wl3, vh0,vh1);
        }
    }

    // D layout: oc0=(q0+gid, ch=2c4), oc1=(.., 2c4+1), oc2=(+8, 2c4), oc3=(+8, 2c4+1)
    float* Ob = g_op[kseg] + base;
    Ob[(size_t)(2 * c4)     * LL + q0 + gid]     = oc0;
    Ob[(size_t)(2 * c4 + 1) * LL + q0 + gid]     = oc1;
    Ob[(size_t)(2 * c4)     * LL + q0 + gid + 8] = oc2;
    Ob[(size_t)(2 * c4 + 1) * LL + q0 + gid + 8] = oc3;
}

// ---------------------------------------------------------------------------
// K5: reduce the 2 k-segment partials.
// ---------------------------------------------------------------------------
__global__ __launch_bounds__(256) void k_reduce2()
{
    const int i = blockIdx.x * 256 + threadIdx.x;  // over BCHL/4 = 73728
    float4 a = ((const float4*)g_op[0])[i];
    float4 t = ((const float4*)g_op[1])[i];
    a.x += t.x; a.y += t.y; a.z += t.z; a.w += t.w;
    ((float4*)g_o)[i] = a;
}

// ---------------------------------------------------------------------------
// K6: output 1x1 conv.  grid = 288 x 256.  (R7, proven)
// ---------------------------------------------------------------------------
__global__ __launch_bounds__(256) void k_oconv(
    const float* __restrict__ Wo, const float* __restrict__ bo,
    float* __restrict__ out)
{
    __shared__ __align__(16) float sW[64*64];
    __shared__ float sb[64];
    const int tid = threadIdx.x;
    for (int i = tid; i < 4096; i += 256) sW[i] = Wo[i];
    if (tid < 64) sb[tid] = bo[tid];
    __syncthreads();

    const int col = blockIdx.x * 16 + (tid & 15);
    const int og  = tid >> 4;
    const int b   = col / LL;
    const int l   = col - b * LL;

    const float* xp = g_o + (size_t)b * CH * LL + l;
    float xr[64];
#pragma unroll
    for (int c = 0; c < 64; c++) xr[c] = xp[c * LL];

#pragma unroll
    for (int j = 0; j < 4; j++) {
        const int o = og * 4 + j;
        const float4* wr = (const float4*)&sW[o * 64];
        float a0 = 0.f, a1 = 0.f, a2 = 0.f, a3 = 0.f;
#pragma unroll
        for (int c4 = 0; c4 < 16; c4++) {
            float4 w = wr[c4];
            a0 = fmaf(w.x, xr[c4*4+0], a0);
            a1 = fmaf(w.y, xr[c4*4+1], a1);
            a2 = fmaf(w.z, xr[c4*4+2], a2);
            a3 = fmaf(w.w, xr[c4*4+3], a3);
        }
        out[((size_t)b * CH + o) * LL + l] = (a0 + a1) + (a2 + a3) + sb[o];
    }
}

// ---------------------------------------------------------------------------
extern "C" void kernel_launch(void* const* d_in, const int* in_sizes, int n_in,
                              void* d_out, int out_size)
{
    const float* x  = (const float*)d_in[0];
    const float* Wq = (const float*)d_in[1];
    const float* bq = (const float*)d_in[2];
    const float* Wk = (const float*)d_in[3];
    const float* bk = (const float*)d_in[4];
    const float* Wv = (const float*)d_in[5];
    const float* bv = (const float*)d_in[6];
    const float* Wo = (const float*)d_in[7];
    const float* bo = (const float*)d_in[8];

    float* out   = (float*)d_out;           // first output: conv result
    float* q_out = (float*)d_out + BCHL;    // second output: scaled q

    k_qkv<<<288, 256>>>(x, Wq, bq, Wk, bk, Wv, bv, q_out);
    k_passA<<<dim3(16, 2, SEGS), 288>>>();
    k_zsum<<<144, 256>>>();
    k_passB<<<dim3(16, 18, 2), 256>>>();
    k_reduce2<<<288, 256>>>();
    k_oconv<<<288, 256>>>(Wo, bo, out);
}

// round 11
// speedup vs baseline: 1.9912x; 1.1063x over previous
#include <cuda_runtime.h>
#include <cuda_fp16.h>

// Problem constants (fixed by the reference setup)
#define BB   2
#define CH   64
#define NH   8
#define DH   8
#define HW   48
#define LL   2304            // HW*HW
#define BCHL (BB*CH*LL)      // 294912

#define LOG2E 1.4426950408889634f

#define EX2F(r,x)     asm("ex2.approx.ftz.f32 %0,%1;"  : "=f"(r) : "f"(x))
#define CVT_TF32(u,x) asm("cvt.rna.tf32.f32 %0,%1;"    : "=r"(u) : "f"(x))
// d = {hi=cvt(a), lo=cvt(b)}
#define PACK_F16X2(d,a,b) asm("cvt.rn.f16x2.f32 %0,%1,%2;" : "=r"(d) : "f"(a), "f"(b))

#define MMA_TF32(d0,d1,d2,d3,a0,a1,a2,a3,b0,b1) \
  asm volatile("mma.sync.aligned.m16n8k8.row.col.f32.tf32.tf32.f32 " \
    "{%0,%1,%2,%3},{%4,%5,%6,%7},{%8,%9},{%0,%1,%2,%3};" \
    : "+f"(d0),"+f"(d1),"+f"(d2),"+f"(d3) \
    : "r"(a0),"r"(a1),"r"(a2),"r"(a3),"r"(b0),"r"(b1))

#define MMA_F16(d0,d1,d2,d3,a0,a1,a2,a3,b0,b1) \
  asm volatile("mma.sync.aligned.m16n8k16.row.col.f32.f16.f16.f32 " \
    "{%0,%1,%2,%3},{%4,%5,%6,%7},{%8,%9},{%0,%1,%2,%3};" \
    : "+f"(d0),"+f"(d1),"+f"(d2),"+f"(d3) \
    : "r"(a0),"r"(a1),"r"(a2),"r"(a3),"r"(b0),"r"(b1))

typedef unsigned int u32;

// Scratch (device globals — no allocation allowed)
__device__ float g_q [BCHL];          // q * d^-0.5 * log2(e)  (for EX2)
__device__ float g_k [BCHL];
__device__ float g_v [BCHL];
__device__ float g_o [BCHL];
__device__ float g_Z [2][BB*NH][LL];  // 2 q-split partials
__device__ float g_zinv[BB*NH*LL];
__device__ float g_op[2][BCHL];

// ---------------------------------------------------------------------------
// K1: fused q/k/v 1x1 convs.  grid = 288 blocks x 256 thr.  (proven)
// ---------------------------------------------------------------------------
__global__ __launch_bounds__(256) void k_qkv(
    const float* __restrict__ x,
    const float* __restrict__ Wq, const float* __restrict__ bq,
    const float* __restrict__ Wk, const float* __restrict__ bk,
    const float* __restrict__ Wv, const float* __restrict__ bv,
    float* __restrict__ q_out)
{
    __shared__ __align__(16) float sW[3][64*64];
    __shared__ float sb[3][64];
    const int tid = threadIdx.x;
    for (int i = tid; i < 4096; i += 256) {
        sW[0][i] = Wq[i]; sW[1][i] = Wk[i]; sW[2][i] = Wv[i];
    }
    if (tid < 64) { sb[0][tid] = bq[tid]; sb[1][tid] = bk[tid]; sb[2][tid] = bv[tid]; }
    __syncthreads();

    const int col = blockIdx.x * 16 + (tid & 15);
    const int og  = tid >> 4;
    const int b   = col / LL;
    const int l   = col - b * LL;

    const float* xp = x + (size_t)b * CH * LL + l;
    float xr[64];
#pragma unroll
    for (int c = 0; c < 64; c++) xr[c] = xp[c * LL];

    const float qscale = 0.35355339059327373f;  // 8^-0.5

#pragma unroll
    for (int m = 0; m < 3; m++) {
        float* dst = (m == 0) ? g_q : (m == 1) ? g_k : g_v;
#pragma unroll
        for (int j = 0; j < 4; j++) {
            const int o = og * 4 + j;
            const float4* wr = (const float4*)&sW[m][o * 64];
            float a0 = 0.f, a1 = 0.f, a2 = 0.f, a3 = 0.f;
#pragma unroll
            for (int c4 = 0; c4 < 16; c4++) {
                float4 w = wr[c4];
                a0 = fmaf(w.x, xr[c4*4+0], a0);
                a1 = fmaf(w.y, xr[c4*4+1], a1);
                a2 = fmaf(w.z, xr[c4*4+2], a2);
                a3 = fmaf(w.w, xr[c4*4+3], a3);
            }
            float r = (a0 + a1) + (a2 + a3) + sb[m][o];
            const size_t idx = ((size_t)b * CH + o) * LL + l;
            if (m == 0) {
                float rq = r * qscale;
                q_out[idx] = rq;                 // reference returns the SCALED q
                dst[idx]   = rq * LOG2E;         // internal: prescaled for EX2
            } else {
                dst[idx] = r;
            }
        }
    }
}

// ---------------------------------------------------------------------------
// K2 (pass A): tensor-core Z.  Warp owns 16 k-cols (two fixed B-frag groups),
// loops q in 128-wide SMEM chunks (hi/lo tf32 split in the fill).
// Per 16q tile: 6 tf32 mma + 8 EX2 + FADD accumulate; final shfl-xor
// reduction over the 8 q-rows-lanes -> Z partial for this q-half.
// grid = (bh=16, kblk=18, qseg=2) x 256 thr.
// ---------------------------------------------------------------------------
__global__ __launch_bounds__(256) void k_passA()
{
    const int bh = blockIdx.x;
    const int b = bh >> 3, h = bh & 7;
    const size_t base = (size_t)(b * CH + h * DH) * LL;
    const int tid  = threadIdx.x;
    const int lane = tid & 31, wid = tid >> 5;
    const int c4 = lane & 3, gid = lane >> 2;
    const int wk = blockIdx.y * 128 + wid * 16;  // this warp's 16 k-cols
    const int qs = blockIdx.z;

    // Two fixed B-fragment groups (K hi/lo), cols [wk,wk+8) and [wk+8,wk+16)
    u32 bhA0, bhA1, blA0, blA1, bhB0, bhB1, blB0, blB1;
    {
        float f;
        f = g_k[base + (size_t)c4       * LL + wk + gid];
        CVT_TF32(bhA0, f); blA0 = __float_as_uint(f - __uint_as_float(bhA0));
        f = g_k[base + (size_t)(c4 + 4) * LL + wk + gid];
        CVT_TF32(bhA1, f); blA1 = __float_as_uint(f - __uint_as_float(bhA1));
        f = g_k[base + (size_t)c4       * LL + wk + 8 + gid];
        CVT_TF32(bhB0, f); blB0 = __float_as_uint(f - __uint_as_float(bhB0));
        f = g_k[base + (size_t)(c4 + 4) * LL + wk + 8 + gid];
        CVT_TF32(bhB1, f); blB1 = __float_as_uint(f - __uint_as_float(bhB1));
    }

    __shared__ float sqh[8][136], sql[8][136];

    float zA0 = 0.f, zA1 = 0.f, zB0 = 0.f, zB1 = 0.f;

    for (int chunk = 0; chunk < 9; chunk++) {
        const int q0 = qs * 1152 + chunk * 128;
        __syncthreads();
        for (int i = tid; i < 1024; i += 256) {
            const int d = i >> 7, qq = i & 127;
            float f = g_q[base + (size_t)d * LL + q0 + qq];
            u32 hb; CVT_TF32(hb, f);
            float hi = __uint_as_float(hb);
            sqh[d][qq] = hi;
            sql[d][qq] = f - hi;
        }
        __syncthreads();

#pragma unroll
        for (int qt = 0; qt < 8; qt++) {
            const int qq = qt * 16 + gid;
            const u32 ah0 = __float_as_uint(sqh[c4][qq]);
            const u32 ah1 = __float_as_uint(sqh[c4][qq + 8]);
            const u32 ah2 = __float_as_uint(sqh[c4 + 4][qq]);
            const u32 ah3 = __float_as_uint(sqh[c4 + 4][qq + 8]);
            const u32 al0 = __float_as_uint(sql[c4][qq]);
            const u32 al1 = __float_as_uint(sql[c4][qq + 8]);
            const u32 al2 = __float_as_uint(sql[c4 + 4][qq]);
            const u32 al3 = __float_as_uint(sql[c4 + 4][qq + 8]);

            float pA0 = 0.f, pA1 = 0.f, pA2 = 0.f, pA3 = 0.f;
            float pB0 = 0.f, pB1 = 0.f, pB2 = 0.f, pB3 = 0.f;
            MMA_TF32(pA0,pA1,pA2,pA3, ah0,ah1,ah2,ah3, bhA0,bhA1);
            MMA_TF32(pB0,pB1,pB2,pB3, ah0,ah1,ah2,ah3, bhB0,bhB1);
            MMA_TF32(pA0,pA1,pA2,pA3, ah0,ah1,ah2,ah3, blA0,blA1);
            MMA_TF32(pB0,pB1,pB2,pB3, ah0,ah1,ah2,ah3, blB0,blB1);
            MMA_TF32(pA0,pA1,pA2,pA3, al0,al1,al2,al3, bhA0,bhA1);
            MMA_TF32(pB0,pB1,pB2,pB3, al0,al1,al2,al3, bhB0,bhB1);

            float e0,e1,e2,e3,f0,f1,f2,f3;
            EX2F(e0,pA0); EX2F(e1,pA1); EX2F(e2,pA2); EX2F(e3,pA3);
            EX2F(f0,pB0); EX2F(f1,pB1); EX2F(f2,pB2); EX2F(f3,pB3);
            zA0 += e0 + e2;   // col wk + 2c4
            zA1 += e1 + e3;   // col wk + 2c4 + 1
            zB0 += f0 + f2;   // col wk + 8 + 2c4
            zB1 += f1 + f3;   // col wk + 8 + 2c4 + 1
        }
    }

    // reduce over the 8 gid-lanes sharing each column (lanes with same c4)
    zA0 += __shfl_xor_sync(0xffffffffu, zA0, 4);
    zA0 += __shfl_xor_sync(0xffffffffu, zA0, 8);
    zA0 += __shfl_xor_sync(0xffffffffu, zA0, 16);
    zA1 += __shfl_xor_sync(0xffffffffu, zA1, 4);
    zA1 += __shfl_xor_sync(0xffffffffu, zA1, 8);
    zA1 += __shfl_xor_sync(0xffffffffu, zA1, 16);
    zB0 += __shfl_xor_sync(0xffffffffu, zB0, 4);
    zB0 += __shfl_xor_sync(0xffffffffu, zB0, 8);
    zB0 += __shfl_xor_sync(0xffffffffu, zB0, 16);
    zB1 += __shfl_xor_sync(0xffffffffu, zB1, 4);
    zB1 += __shfl_xor_sync(0xffffffffu, zB1, 8);
    zB1 += __shfl_xor_sync(0xffffffffu, zB1, 16);

    if (lane < 4) {
        float* Zp = &g_Z[qs][bh][0];
        Zp[wk + 2 * lane]         = zA0;
        Zp[wk + 2 * lane + 1]     = zA1;
        Zp[wk + 8 + 2 * lane]     = zB0;
        Zp[wk + 8 + 2 * lane + 1] = zB1;
    }
}

// ---------------------------------------------------------------------------
// K3: sum the 2 Z partials -> 1/Z per (bh, k).  36864 threads.
// ---------------------------------------------------------------------------
__global__ __launch_bounds__(256) void k_zsum()
{
    const int t = blockIdx.x * 256 + threadIdx.x;  // == bh*LL + k
    const float* Zf = (const float*)g_Z;
    g_zinv[t] = 1.0f / (Zf[t] + Zf[(size_t)(BB*NH) * LL + t]);
}

// ---------------------------------------------------------------------------
// K4 (pass B): tensor-core (proven R10).  3x tf32 mma logits -> EX2 ->
// in-place f16 A-frag -> 3x f16 mma AV with V' = v/Z staged in SMEM.
// grid = (bh=16, qblk=18, kseg=2) x 256 thr.
// ---------------------------------------------------------------------------
__global__ __launch_bounds__(256) void k_passB()
{
    const int bh = blockIdx.x;
    const int b = bh >> 3, h = bh & 7;
    const size_t base = (size_t)(b * CH + h * DH) * LL;
    const int tid  = threadIdx.x;
    const int lane = tid & 31, wid = tid >> 5;
    const int c4 = lane & 3, gid = lane >> 2;
    const int q0 = blockIdx.y * 128 + wid * 16;
    const int kseg = blockIdx.z;

    // Q A-fragments (tf32 hi + f32 residual), rows=q, cols=d
    u32 ah[4], al[4];
    {
        float f0 = g_q[base + (size_t)c4 * LL + q0 + gid];
        float f1 = g_q[base + (size_t)c4 * LL + q0 + gid + 8];
        float f2 = g_q[base + (size_t)(c4 + 4) * LL + q0 + gid];
        float f3 = g_q[base + (size_t)(c4 + 4) * LL + q0 + gid + 8];
        CVT_TF32(ah[0], f0); al[0] = __float_as_uint(f0 - __uint_as_float(ah[0]));
        CVT_TF32(ah[1], f1); al[1] = __float_as_uint(f1 - __uint_as_float(ah[1]));
        CVT_TF32(ah[2], f2); al[2] = __float_as_uint(f2 - __uint_as_float(ah[2]));
        CVT_TF32(ah[3], f3); al[3] = __float_as_uint(f3 - __uint_as_float(ah[3]));
    }

    __shared__ float  skhi[8][136], sklo[8][136];
    __shared__ __half svh [8][136], svl [8][136];

    const int fkk = tid & 127;      // fixed k column this thread fills
    const int fd0 = tid >> 7;       // starting row (0/1), step 2

    float oc0 = 0.f, oc1 = 0.f, oc2 = 0.f, oc3 = 0.f;

    for (int chunk = 0; chunk < 9; chunk++) {
        const int kc = kseg * 1152 + chunk * 128;
        __syncthreads();
        {
            const float zi = g_zinv[(size_t)bh * LL + kc + fkk];
#pragma unroll
            for (int j = 0; j < 4; j++) {
                const int d = fd0 + 2 * j;
                float kvf = g_k[base + (size_t)d * LL + kc + fkk];
                u32 hb; CVT_TF32(hb, kvf);
                float hi = __uint_as_float(hb);
                skhi[d][fkk] = hi;
                sklo[d][fkk] = kvf - hi;
                float vv = g_v[base + (size_t)d * LL + kc + fkk] * zi;
                __half vh = __float2half_rn(vv);
                svh[d][fkk] = vh;
                svl[d][fkk] = __float2half_rn(vv - __half2float(vh));
            }
        }
        __syncthreads();

#pragma unroll
        for (int kt = 0; kt < 8; kt++) {
            const int kx0 = kt * 16 + gid;
            const int kx1 = kx0 + 8;
            const u32 b00 = __float_as_uint(skhi[c4][kx0]);
            const u32 b01 = __float_as_uint(skhi[c4 + 4][kx0]);
            const u32 l00 = __float_as_uint(sklo[c4][kx0]);
            const u32 l01 = __float_as_uint(sklo[c4 + 4][kx0]);
            const u32 b10 = __float_as_uint(skhi[c4][kx1]);
            const u32 b11 = __float_as_uint(skhi[c4 + 4][kx1]);
            const u32 l10 = __float_as_uint(sklo[c4][kx1]);
            const u32 l11 = __float_as_uint(sklo[c4 + 4][kx1]);

            float p0 = 0.f, p1 = 0.f, p2 = 0.f, p3 = 0.f;
            MMA_TF32(p0,p1,p2,p3, ah[0],ah[1],ah[2],ah[3], b00,b01);
            MMA_TF32(p0,p1,p2,p3, ah[0],ah[1],ah[2],ah[3], l00,l01);
            MMA_TF32(p0,p1,p2,p3, al[0],al[1],al[2],al[3], b00,b01);
            float r0 = 0.f, r1 = 0.f, r2 = 0.f, r3 = 0.f;
            MMA_TF32(r0,r1,r2,r3, ah[0],ah[1],ah[2],ah[3], b10,b11);
            MMA_TF32(r0,r1,r2,r3, ah[0],ah[1],ah[2],ah[3], l10,l11);
            MMA_TF32(r0,r1,r2,r3, al[0],al[1],al[2],al[3], b10,b11);

            float e0,e1,e2,e3,f0,f1,f2,f3;
            EX2F(e0,p0); EX2F(e1,p1); EX2F(e2,p2); EX2F(e3,p3);
            EX2F(f0,r0); EX2F(f1,r1); EX2F(f2,r2); EX2F(f3,r3);

            // wh: f16 A-fragment (C layout == A layout, no shuffles)
            u32 wh0, wh1, wh2, wh3;
            PACK_F16X2(wh0, e1, e0);
            PACK_F16X2(wh1, e3, e2);
            PACK_F16X2(wh2, f1, f0);
            PACK_F16X2(wh3, f3, f2);

            // wl: f16 residual fragment
            u32 wl0, wl1, wl2, wl3;
            {
                float2 g;
                g = __half22float2(*reinterpret_cast<__half2*>(&wh0));
                PACK_F16X2(wl0, e1 - g.y, e0 - g.x);
                g = __half22float2(*reinterpret_cast<__half2*>(&wh1));
                PACK_F16X2(wl1, e3 - g.y, e2 - g.x);
                g = __half22float2(*reinterpret_cast<__half2*>(&wh2));
                PACK_F16X2(wl2, f1 - g.y, f0 - g.x);
                g = __half22float2(*reinterpret_cast<__half2*>(&wh3));
                PACK_F16X2(wl3, f3 - g.y, f2 - g.x);
            }

            // V' B-fragments (f16 hi/lo): b0 = k rows {2c4,2c4+1}, b1 = +8
            const u32 vh0 = *reinterpret_cast<const u32*>(&svh[gid][kt * 16 + 2 * c4]);
            const u32 vh1 = *reinterpret_cast<const u32*>(&svh[gid][kt * 16 + 2 * c4 + 8]);
            const u32 vl0 = *reinterpret_cast<const u32*>(&svl[gid][kt * 16 + 2 * c4]);
            const u32 vl1 = *reinterpret_cast<const u32*>(&svl[gid][kt * 16 + 2 * c4 + 8]);

            MMA_F16(oc0,oc1,oc2,oc3, wh0,wh1,wh2,wh3, vh0,vh1);
            MMA_F16(oc0,oc1,oc2,oc3, wh0,wh1,wh2,wh3, vl0,vl1);
            MMA_F16(oc0,oc1,oc2,oc3, wl0,wl1,wl2,wl3, vh0,vh1);
        }
    }

    float* Ob = g_op[kseg] + base;
    Ob[(size_t)(2 * c4)     * LL + q0 + gid]     = oc0;
    Ob[(size_t)(2 * c4 + 1) * LL + q0 + gid]     = oc1;
    Ob[(size_t)(2 * c4)     * LL + q0 + gid + 8] = oc2;
    Ob[(size_t)(2 * c4 + 1) * LL + q0 + gid + 8] = oc3;
}

// ---------------------------------------------------------------------------
// K5: reduce the 2 k-segment partials.
// ---------------------------------------------------------------------------
__global__ __launch_bounds__(256) void k_reduce2()
{
    const int i = blockIdx.x * 256 + threadIdx.x;  // over BCHL/4 = 73728
    float4 a = ((const float4*)g_op[0])[i];
    float4 t = ((const float4*)g_op[1])[i];
    a.x += t.x; a.y += t.y; a.z += t.z; a.w += t.w;
    ((float4*)g_o)[i] = a;
}

// ---------------------------------------------------------------------------
// K6: output 1x1 conv.  grid = 288 x 256.  (proven)
// ---------------------------------------------------------------------------
__global__ __launch_bounds__(256) void k_oconv(
    const float* __restrict__ Wo, const float* __restrict__ bo,
    float* __restrict__ out)
{
    __shared__ __align__(16) float sW[64*64];
    __shared__ float sb[64];
    const int tid = threadIdx.x;
    for (int i = tid; i < 4096; i += 256) sW[i] = Wo[i];
    if (tid < 64) sb[tid] = bo[tid];
    __syncthreads();

    const int col = blockIdx.x * 16 + (tid & 15);
    const int og  = tid >> 4;
    const int b   = col / LL;
    const int l   = col - b * LL;

    const float* xp = g_o + (size_t)b * CH * LL + l;
    float xr[64];
#pragma unroll
    for (int c = 0; c < 64; c++) xr[c] = xp[c * LL];

#pragma unroll
    for (int j = 0; j < 4; j++) {
        const int o = og * 4 + j;
        const float4* wr = (const float4*)&sW[o * 64];
        float a0 = 0.f, a1 = 0.f, a2 = 0.f, a3 = 0.f;
#pragma unroll
        for (int c4 = 0; c4 < 16; c4++) {
            float4 w = wr[c4];
            a0 = fmaf(w.x, xr[c4*4+0], a0);
            a1 = fmaf(w.y, xr[c4*4+1], a1);
            a2 = fmaf(w.z, xr[c4*4+2], a2);
            a3 = fmaf(w.w, xr[c4*4+3], a3);
        }
        out[((size_t)b * CH + o) * LL + l] = (a0 + a1) + (a2 + a3) + sb[o];
    }
}

// ---------------------------------------------------------------------------
extern "C" void kernel_launch(void* const* d_in, const int* in_sizes, int n_in,
                              void* d_out, int out_size)
{
    const float* x  = (const float*)d_in[0];
    const float* Wq = (const float*)d_in[1];
    const float* bq = (const float*)d_in[2];
    const float* Wk = (const float*)d_in[3];
    const float* bk = (const float*)d_in[4];
    const float* Wv = (const float*)d_in[5];
    const float* bv = (const float*)d_in[6];
    const float* Wo = (const float*)d_in[7];
    const float* bo = (const float*)d_in[8];

    float* out   = (float*)d_out;           // first output: conv result
    float* q_out = (float*)d_out + BCHL;    // second output: scaled q

    k_qkv<<<288, 256>>>(x, Wq, bq, Wk, bk, Wv, bv, q_out);
    k_passA<<<dim3(16, 18, 2), 256>>>();
    k_zsum<<<144, 256>>>();
    k_passB<<<dim3(16, 18, 2), 256>>>();
    k_reduce2<<<288, 256>>>();
    k_oconv<<<288, 256>>>(Wo, bo, out);
}

// round 12
// speedup vs baseline: 2.1356x; 1.0725x over previous
#include <cuda_runtime.h>
#include <cuda_fp16.h>

// Problem constants (fixed by the reference setup)
#define BB   2
#define CH   64
#define NH   8
#define DH   8
#define HW   48
#define LL   2304            // HW*HW
#define BCHL (BB*CH*LL)      // 294912

#define LOG2E 1.4426950408889634f

#define EX2F(r,x)     asm("ex2.approx.ftz.f32 %0,%1;"  : "=f"(r) : "f"(x))
#define CVT_TF32(u,x) asm("cvt.rna.tf32.f32 %0,%1;"    : "=r"(u) : "f"(x))
// d = {hi=cvt(a), lo=cvt(b)}
#define PACK_F16X2(d,a,b) asm("cvt.rn.f16x2.f32 %0,%1,%2;" : "=r"(d) : "f"(a), "f"(b))

#define MMA_TF32(d0,d1,d2,d3,a0,a1,a2,a3,b0,b1) \
  asm volatile("mma.sync.aligned.m16n8k8.row.col.f32.tf32.tf32.f32 " \
    "{%0,%1,%2,%3},{%4,%5,%6,%7},{%8,%9},{%0,%1,%2,%3};" \
    : "+f"(d0),"+f"(d1),"+f"(d2),"+f"(d3) \
    : "r"(a0),"r"(a1),"r"(a2),"r"(a3),"r"(b0),"r"(b1))

#define MMA_F16(d0,d1,d2,d3,a0,a1,a2,a3,b0,b1) \
  asm volatile("mma.sync.aligned.m16n8k16.row.col.f32.f16.f16.f32 " \
    "{%0,%1,%2,%3},{%4,%5,%6,%7},{%8,%9},{%0,%1,%2,%3};" \
    : "+f"(d0),"+f"(d1),"+f"(d2),"+f"(d3) \
    : "r"(a0),"r"(a1),"r"(a2),"r"(a3),"r"(b0),"r"(b1))

typedef unsigned int u32;

// Scratch (device globals — no allocation allowed)
__device__ float g_q [BCHL];          // q * d^-0.5 * log2(e)  (for EX2)
__device__ float g_k [BCHL];
__device__ float g_v [BCHL];
__device__ float g_o [BCHL];
__device__ float g_Z [2][BB*NH][LL];  // 2 q-split partials
__device__ float g_zinv[BB*NH*LL];
__device__ float g_op[2][BCHL];

// ---------------------------------------------------------------------------
// K1: fused q/k/v 1x1 convs.  grid = 288 blocks x 256 thr.  (proven)
// ---------------------------------------------------------------------------
__global__ __launch_bounds__(256) void k_qkv(
    const float* __restrict__ x,
    const float* __restrict__ Wq, const float* __restrict__ bq,
    const float* __restrict__ Wk, const float* __restrict__ bk,
    const float* __restrict__ Wv, const float* __restrict__ bv,
    float* __restrict__ q_out)
{
    __shared__ __align__(16) float sW[3][64*64];
    __shared__ float sb[3][64];
    const int tid = threadIdx.x;
    for (int i = tid; i < 4096; i += 256) {
        sW[0][i] = Wq[i]; sW[1][i] = Wk[i]; sW[2][i] = Wv[i];
    }
    if (tid < 64) { sb[0][tid] = bq[tid]; sb[1][tid] = bk[tid]; sb[2][tid] = bv[tid]; }
    __syncthreads();

    const int col = blockIdx.x * 16 + (tid & 15);
    const int og  = tid >> 4;
    const int b   = col / LL;
    const int l   = col - b * LL;

    const float* xp = x + (size_t)b * CH * LL + l;
    float xr[64];
#pragma unroll
    for (int c = 0; c < 64; c++) xr[c] = xp[c * LL];

    const float qscale = 0.35355339059327373f;  // 8^-0.5

#pragma unroll
    for (int m = 0; m < 3; m++) {
        float* dst = (m == 0) ? g_q : (m == 1) ? g_k : g_v;
#pragma unroll
        for (int j = 0; j < 4; j++) {
            const int o = og * 4 + j;
            const float4* wr = (const float4*)&sW[m][o * 64];
            float a0 = 0.f, a1 = 0.f, a2 = 0.f, a3 = 0.f;
#pragma unroll
            for (int c4 = 0; c4 < 16; c4++) {
                float4 w = wr[c4];
                a0 = fmaf(w.x, xr[c4*4+0], a0);
                a1 = fmaf(w.y, xr[c4*4+1], a1);
                a2 = fmaf(w.z, xr[c4*4+2], a2);
                a3 = fmaf(w.w, xr[c4*4+3], a3);
            }
            float r = (a0 + a1) + (a2 + a3) + sb[m][o];
            const size_t idx = ((size_t)b * CH + o) * LL + l;
            if (m == 0) {
                float rq = r * qscale;
                q_out[idx] = rq;                 // reference returns the SCALED q
                dst[idx]   = rq * LOG2E;         // internal: prescaled for EX2
            } else {
                dst[idx] = r;
            }
        }
    }
}

// ---------------------------------------------------------------------------
// K2 (pass A): tensor-core Z (proven R11).
// grid = (bh=16, kblk=18, qseg=2) x 256 thr.
// ---------------------------------------------------------------------------
__global__ __launch_bounds__(256) void k_passA()
{
    const int bh = blockIdx.x;
    const int b = bh >> 3, h = bh & 7;
    const size_t base = (size_t)(b * CH + h * DH) * LL;
    const int tid  = threadIdx.x;
    const int lane = tid & 31, wid = tid >> 5;
    const int c4 = lane & 3, gid = lane >> 2;
    const int wk = blockIdx.y * 128 + wid * 16;  // this warp's 16 k-cols
    const int qs = blockIdx.z;

    // Two fixed B-fragment groups (K hi/lo), cols [wk,wk+8) and [wk+8,wk+16)
    u32 bhA0, bhA1, blA0, blA1, bhB0, bhB1, blB0, blB1;
    {
        float f;
        f = g_k[base + (size_t)c4       * LL + wk + gid];
        CVT_TF32(bhA0, f); blA0 = __float_as_uint(f - __uint_as_float(bhA0));
        f = g_k[base + (size_t)(c4 + 4) * LL + wk + gid];
        CVT_TF32(bhA1, f); blA1 = __float_as_uint(f - __uint_as_float(bhA1));
        f = g_k[base + (size_t)c4       * LL + wk + 8 + gid];
        CVT_TF32(bhB0, f); blB0 = __float_as_uint(f - __uint_as_float(bhB0));
        f = g_k[base + (size_t)(c4 + 4) * LL + wk + 8 + gid];
        CVT_TF32(bhB1, f); blB1 = __float_as_uint(f - __uint_as_float(bhB1));
    }

    __shared__ float sqh[8][136], sql[8][136];

    float zA0 = 0.f, zA1 = 0.f, zB0 = 0.f, zB1 = 0.f;

    for (int chunk = 0; chunk < 9; chunk++) {
        const int q0 = qs * 1152 + chunk * 128;
        __syncthreads();
        for (int i = tid; i < 1024; i += 256) {
            const int d = i >> 7, qq = i & 127;
            float f = g_q[base + (size_t)d * LL + q0 + qq];
            u32 hb; CVT_TF32(hb, f);
            float hi = __uint_as_float(hb);
            sqh[d][qq] = hi;
            sql[d][qq] = f - hi;
        }
        __syncthreads();

#pragma unroll
        for (int qt = 0; qt < 8; qt++) {
            const int qq = qt * 16 + gid;
            const u32 ah0 = __float_as_uint(sqh[c4][qq]);
            const u32 ah1 = __float_as_uint(sqh[c4][qq + 8]);
            const u32 ah2 = __float_as_uint(sqh[c4 + 4][qq]);
            const u32 ah3 = __float_as_uint(sqh[c4 + 4][qq + 8]);
            const u32 al0 = __float_as_uint(sql[c4][qq]);
            const u32 al1 = __float_as_uint(sql[c4][qq + 8]);
            const u32 al2 = __float_as_uint(sql[c4 + 4][qq]);
            const u32 al3 = __float_as_uint(sql[c4 + 4][qq + 8]);

            float pA0 = 0.f, pA1 = 0.f, pA2 = 0.f, pA3 = 0.f;
            float pB0 = 0.f, pB1 = 0.f, pB2 = 0.f, pB3 = 0.f;
            MMA_TF32(pA0,pA1,pA2,pA3, ah0,ah1,ah2,ah3, bhA0,bhA1);
            MMA_TF32(pB0,pB1,pB2,pB3, ah0,ah1,ah2,ah3, bhB0,bhB1);
            MMA_TF32(pA0,pA1,pA2,pA3, ah0,ah1,ah2,ah3, blA0,blA1);
            MMA_TF32(pB0,pB1,pB2,pB3, ah0,ah1,ah2,ah3, blB0,blB1);
            MMA_TF32(pA0,pA1,pA2,pA3, al0,al1,al2,al3, bhA0,bhA1);
            MMA_TF32(pB0,pB1,pB2,pB3, al0,al1,al2,al3, bhB0,bhB1);

            float e0,e1,e2,e3,f0,f1,f2,f3;
            EX2F(e0,pA0); EX2F(e1,pA1); EX2F(e2,pA2); EX2F(e3,pA3);
            EX2F(f0,pB0); EX2F(f1,pB1); EX2F(f2,pB2); EX2F(f3,pB3);
            zA0 += e0 + e2;   // col wk + 2c4
            zA1 += e1 + e3;   // col wk + 2c4 + 1
            zB0 += f0 + f2;   // col wk + 8 + 2c4
            zB1 += f1 + f3;   // col wk + 8 + 2c4 + 1
        }
    }

    // reduce over the 8 gid-lanes sharing each column (lanes with same c4)
    zA0 += __shfl_xor_sync(0xffffffffu, zA0, 4);
    zA0 += __shfl_xor_sync(0xffffffffu, zA0, 8);
    zA0 += __shfl_xor_sync(0xffffffffu, zA0, 16);
    zA1 += __shfl_xor_sync(0xffffffffu, zA1, 4);
    zA1 += __shfl_xor_sync(0xffffffffu, zA1, 8);
    zA1 += __shfl_xor_sync(0xffffffffu, zA1, 16);
    zB0 += __shfl_xor_sync(0xffffffffu, zB0, 4);
    zB0 += __shfl_xor_sync(0xffffffffu, zB0, 8);
    zB0 += __shfl_xor_sync(0xffffffffu, zB0, 16);
    zB1 += __shfl_xor_sync(0xffffffffu, zB1, 4);
    zB1 += __shfl_xor_sync(0xffffffffu, zB1, 8);
    zB1 += __shfl_xor_sync(0xffffffffu, zB1, 16);

    if (lane < 4) {
        float* Zp = &g_Z[qs][bh][0];
        Zp[wk + 2 * lane]         = zA0;
        Zp[wk + 2 * lane + 1]     = zA1;
        Zp[wk + 8 + 2 * lane]     = zB0;
        Zp[wk + 8 + 2 * lane + 1] = zB1;
    }
}

// ---------------------------------------------------------------------------
// K3: sum the 2 Z partials -> 1/Z per (bh, k).  36864 threads.
// ---------------------------------------------------------------------------
__global__ __launch_bounds__(256) void k_zsum()
{
    const int t = blockIdx.x * 256 + threadIdx.x;  // == bh*LL + k
    const float* Zf = (const float*)g_Z;
    g_zinv[t] = 1.0f / (Zf[t] + Zf[(size_t)(BB*NH) * LL + t]);
}

// ---------------------------------------------------------------------------
// K4 (pass B): tensor-core.  3x tf32 mma logits -> EX2 -> in-place f16 A-frag
// -> 2x f16 mma (wh*vh + wh*vl).  P residual dropped: f16 weight quantization
// contributes ~1.5e-4 random rel err, well under the 1e-3 gate, and removes
// ~17 ALU instrs/tile.
// grid = (bh=16, qblk=18, kseg=2) x 256 thr.
// ---------------------------------------------------------------------------
__global__ __launch_bounds__(256) void k_passB()
{
    const int bh = blockIdx.x;
    const int b = bh >> 3, h = bh & 7;
    const size_t base = (size_t)(b * CH + h * DH) * LL;
    const int tid  = threadIdx.x;
    const int lane = tid & 31, wid = tid >> 5;
    const int c4 = lane & 3, gid = lane >> 2;
    const int q0 = blockIdx.y * 128 + wid * 16;
    const int kseg = blockIdx.z;

    // Q A-fragments (tf32 hi + f32 residual), rows=q, cols=d
    u32 ah[4], al[4];
    {
        float f0 = g_q[base + (size_t)c4 * LL + q0 + gid];
        float f1 = g_q[base + (size_t)c4 * LL + q0 + gid + 8];
        float f2 = g_q[base + (size_t)(c4 + 4) * LL + q0 + gid];
        float f3 = g_q[base + (size_t)(c4 + 4) * LL + q0 + gid + 8];
        CVT_TF32(ah[0], f0); al[0] = __float_as_uint(f0 - __uint_as_float(ah[0]));
        CVT_TF32(ah[1], f1); al[1] = __float_as_uint(f1 - __uint_as_float(ah[1]));
        CVT_TF32(ah[2], f2); al[2] = __float_as_uint(f2 - __uint_as_float(ah[2]));
        CVT_TF32(ah[3], f3); al[3] = __float_as_uint(f3 - __uint_as_float(ah[3]));
    }

    __shared__ float  skhi[8][136], sklo[8][136];
    __shared__ __half svh [8][136], svl [8][136];

    const int fkk = tid & 127;      // fixed k column this thread fills
    const int fd0 = tid >> 7;       // starting row (0/1), step 2

    float oc0 = 0.f, oc1 = 0.f, oc2 = 0.f, oc3 = 0.f;

    for (int chunk = 0; chunk < 9; chunk++) {
        const int kc = kseg * 1152 + chunk * 128;
        __syncthreads();
        {
            const float zi = g_zinv[(size_t)bh * LL + kc + fkk];
#pragma unroll
            for (int j = 0; j < 4; j++) {
                const int d = fd0 + 2 * j;
                float kvf = g_k[base + (size_t)d * LL + kc + fkk];
                u32 hb; CVT_TF32(hb, kvf);
                float hi = __uint_as_float(hb);
                skhi[d][fkk] = hi;
                sklo[d][fkk] = kvf - hi;
                float vv = g_v[base + (size_t)d * LL + kc + fkk] * zi;
                __half vh = __float2half_rn(vv);
                svh[d][fkk] = vh;
                svl[d][fkk] = __float2half_rn(vv - __half2float(vh));
            }
        }
        __syncthreads();

#pragma unroll
        for (int kt = 0; kt < 8; kt++) {
            const int kx0 = kt * 16 + gid;
            const int kx1 = kx0 + 8;
            const u32 b00 = __float_as_uint(skhi[c4][kx0]);
            const u32 b01 = __float_as_uint(skhi[c4 + 4][kx0]);
            const u32 l00 = __float_as_uint(sklo[c4][kx0]);
            const u32 l01 = __float_as_uint(sklo[c4 + 4][kx0]);
            const u32 b10 = __float_as_uint(skhi[c4][kx1]);
            const u32 b11 = __float_as_uint(skhi[c4 + 4][kx1]);
            const u32 l10 = __float_as_uint(sklo[c4][kx1]);
            const u32 l11 = __float_as_uint(sklo[c4 + 4][kx1]);

            float p0 = 0.f, p1 = 0.f, p2 = 0.f, p3 = 0.f;
            MMA_TF32(p0,p1,p2,p3, ah[0],ah[1],ah[2],ah[3], b00,b01);
            MMA_TF32(p0,p1,p2,p3, ah[0],ah[1],ah[2],ah[3], l00,l01);
            MMA_TF32(p0,p1,p2,p3, al[0],al[1],al[2],al[3], b00,b01);
            float r0 = 0.f, r1 = 0.f, r2 = 0.f, r3 = 0.f;
            MMA_TF32(r0,r1,r2,r3, ah[0],ah[1],ah[2],ah[3], b10,b11);
            MMA_TF32(r0,r1,r2,r3, ah[0],ah[1],ah[2],ah[3], l10,l11);
            MMA_TF32(r0,r1,r2,r3, al[0],al[1],al[2],al[3], b10,b11);

            float e0,e1,e2,e3,f0,f1,f2,f3;
            EX2F(e0,p0); EX2F(e1,p1); EX2F(e2,p2); EX2F(e3,p3);
            EX2F(f0,r0); EX2F(f1,r1); EX2F(f2,r2); EX2F(f3,r3);

            // wh: f16 A-fragment (C layout == A layout, no shuffles)
            u32 wh0, wh1, wh2, wh3;
            PACK_F16X2(wh0, e1, e0);
            PACK_F16X2(wh1, e3, e2);
            PACK_F16X2(wh2, f1, f0);
            PACK_F16X2(wh3, f3, f2);

            // V' B-fragments (f16 hi/lo): b0 = k rows {2c4,2c4+1}, b1 = +8
            const u32 vh0 = *reinterpret_cast<const u32*>(&svh[gid][kt * 16 + 2 * c4]);
            const u32 vh1 = *reinterpret_cast<const u32*>(&svh[gid][kt * 16 + 2 * c4 + 8]);
            const u32 vl0 = *reinterpret_cast<const u32*>(&svl[gid][kt * 16 + 2 * c4]);
            const u32 vl1 = *reinterpret_cast<const u32*>(&svl[gid][kt * 16 + 2 * c4 + 8]);

            MMA_F16(oc0,oc1,oc2,oc3, wh0,wh1,wh2,wh3, vh0,vh1);
            MMA_F16(oc0,oc1,oc2,oc3, wh0,wh1,wh2,wh3, vl0,vl1);
        }
    }

    float* Ob = g_op[kseg] + base;
    Ob[(size_t)(2 * c4)     * LL + q0 + gid]     = oc0;
    Ob[(size_t)(2 * c4 + 1) * LL + q0 + gid]     = oc1;
    Ob[(size_t)(2 * c4)     * LL + q0 + gid + 8] = oc2;
    Ob[(size_t)(2 * c4 + 1) * LL + q0 + gid + 8] = oc3;
}

// ---------------------------------------------------------------------------
// K5: reduce the 2 k-segment partials.
// ---------------------------------------------------------------------------
__global__ __launch_bounds__(256) void k_reduce2()
{
    const int i = blockIdx.x * 256 + threadIdx.x;  // over BCHL/4 = 73728
    float4 a = ((const float4*)g_op[0])[i];
    float4 t = ((const float4*)g_op[1])[i];
    a.x += t.x; a.y += t.y; a.z += t.z; a.w += t.w;
    ((float4*)g_o)[i] = a;
}

// ---------------------------------------------------------------------------
// K6: output 1x1 conv.  grid = 288 x 256.  (proven)
// ---------------------------------------------------------------------------
__global__ __launch_bounds__(256) void k_oconv(
    const float* __restrict__ Wo, const float* __restrict__ bo,
    float* __restrict__ out)
{
    __shared__ __align__(16) float sW[64*64];
    __shared__ float sb[64];
    const int tid = threadIdx.x;
    for (int i = tid; i < 4096; i += 256) sW[i] = Wo[i];
    if (tid < 64) sb[tid] = bo[tid];
    __syncthreads();

    const int col = blockIdx.x * 16 + (tid & 15);
    const int og  = tid >> 4;
    const int b   = col / LL;
    const int l   = col - b * LL;

    const float* xp = g_o + (size_t)b * CH * LL + l;
    float xr[64];
#pragma unroll
    for (int c = 0; c < 64; c++) xr[c] = xp[c * LL];

#pragma unroll
    for (int j = 0; j < 4; j++) {
        const int o = og * 4 + j;
        const float4* wr = (const float4*)&sW[o * 64];
        float a0 = 0.f, a1 = 0.f, a2 = 0.f, a3 = 0.f;
#pragma unroll
        for (int c4 = 0; c4 < 16; c4++) {
            float4 w = wr[c4];
            a0 = fmaf(w.x, xr[c4*4+0], a0);
            a1 = fmaf(w.y, xr[c4*4+1], a1);
            a2 = fmaf(w.z, xr[c4*4+2], a2);
            a3 = fmaf(w.w, xr[c4*4+3], a3);
        }
        out[((size_t)b * CH + o) * LL + l] = (a0 + a1) + (a2 + a3) + sb[o];
    }
}

// ---------------------------------------------------------------------------
extern "C" void kernel_launch(void* const* d_in, const int* in_sizes, int n_in,
                              void* d_out, int out_size)
{
    const float* x  = (const float*)d_in[0];
    const float* Wq = (const float*)d_in[1];
    const float* bq = (const float*)d_in[2];
    const float* Wk = (const float*)d_in[3];
    const float* bk = (const float*)d_in[4];
    const float* Wv = (const float*)d_in[5];
    const float* bv = (const float*)d_in[6];
    const float* Wo = (const float*)d_in[7];
    const float* bo = (const float*)d_in[8];

    float* out   = (float*)d_out;           // first output: conv result
    float* q_out = (float*)d_out + BCHL;    // second output: scaled q

    k_qkv<<<288, 256>>>(x, Wq, bq, Wk, bk, Wv, bv, q_out);
    k_passA<<<dim3(16, 18, 2), 256>>>();
    k_zsum<<<144, 256>>>();
    k_passB<<<dim3(16, 18, 2), 256>>>();
    k_reduce2<<<288, 256>>>();
    k_oconv<<<288, 256>>>(Wo, bo, out);
}